// round 1
// baseline (speedup 1.0000x reference)
#include <cuda_runtime.h>
#include <cstddef>

#define NN 100000
#define EE 1600000
#define HH 128
#define GG 128

// Scratch in __device__ globals (allocation-free rule).
__device__ float g_h[(size_t)NN * HH];    // layer output
__device__ float g_agg[(size_t)NN * HH];  // aggregation buffer (x + sum_neighbors)
__device__ float g_tmp[(size_t)NN * HH];  // MLP intermediate
__device__ float g_cnt[GG];               // per-graph node counts

// ---------------------------------------------------------------------------
// copy: agg = src  (initializes with self term, scatter adds neighbors)
// ---------------------------------------------------------------------------
__global__ void copy_kernel(const float4* __restrict__ src, float4* __restrict__ dst, int n4) {
    int i = blockIdx.x * blockDim.x + threadIdx.x;
    if (i < n4) dst[i] = src[i];
}

// ---------------------------------------------------------------------------
// scatter: one warp per edge; lane handles 4 consecutive features.
// agg[dst] += h[src]
// ---------------------------------------------------------------------------
__global__ void scatter_kernel(const float* __restrict__ h,
                               const int* __restrict__ src,
                               const int* __restrict__ dst,
                               float* __restrict__ agg) {
    int warp = (blockIdx.x * blockDim.x + threadIdx.x) >> 5;
    int lane = threadIdx.x & 31;
    if (warp >= EE) return;
    int s = __ldg(src + warp);
    int d = __ldg(dst + warp);
    const float4 v = *reinterpret_cast<const float4*>(h + (size_t)s * HH + lane * 4);
    float* p = agg + (size_t)d * HH + lane * 4;
    atomicAdd(p + 0, v.x);
    atomicAdd(p + 1, v.y);
    atomicAdd(p + 2, v.z);
    atomicAdd(p + 3, v.w);
}

// ---------------------------------------------------------------------------
// SGEMM: C[M,128] = op(A[M,128] @ W[128,128] + bias), op = relu or identity
// Tile: BM=128, BN=128 (full), BK=16. 256 threads, 8x8 micro-tile each.
// ---------------------------------------------------------------------------
template <bool RELU>
__global__ __launch_bounds__(256, 2)
void gemm_kernel(const float* __restrict__ A, const float* __restrict__ W,
                 const float* __restrict__ bias, float* __restrict__ C, int M) {
    __shared__ float As[16][129];   // padded: transpose-store conflicts -> <=2-way
    __shared__ float Bs[16][128];

    const int block_m = blockIdx.x * 128;
    const int tid = threadIdx.x;
    const int tx = tid & 15;        // N-tile coord (8 cols each)
    const int ty = tid >> 4;        // M-tile coord (8 rows each)

    float acc[8][8];
    #pragma unroll
    for (int i = 0; i < 8; i++)
        #pragma unroll
        for (int j = 0; j < 8; j++) acc[i][j] = 0.f;

    for (int k0 = 0; k0 < 128; k0 += 16) {
        // Load A tile 128x16 (2048 elems, 8 per thread, row-major coalesced)
        #pragma unroll
        for (int i = 0; i < 8; i++) {
            int e = tid + i * 256;
            int m = e >> 4;
            int k = e & 15;
            int gm = block_m + m;
            As[k][m] = (gm < M) ? A[(size_t)gm * 128 + k0 + k] : 0.f;
        }
        // Load B tile 16x128 (coalesced, conflict-free)
        #pragma unroll
        for (int i = 0; i < 8; i++) {
            int e = tid + i * 256;
            int k = e >> 7;
            int n = e & 127;
            Bs[k][n] = W[(size_t)(k0 + k) * 128 + n];
        }
        __syncthreads();

        #pragma unroll
        for (int k = 0; k < 16; k++) {
            float a[8], b[8];
            #pragma unroll
            for (int i = 0; i < 8; i++) a[i] = As[k][ty * 8 + i];
            #pragma unroll
            for (int j = 0; j < 8; j++) b[j] = Bs[k][tx * 8 + j];
            #pragma unroll
            for (int i = 0; i < 8; i++)
                #pragma unroll
                for (int j = 0; j < 8; j++)
                    acc[i][j] = fmaf(a[i], b[j], acc[i][j]);
        }
        __syncthreads();
    }

    // Epilogue: bias (+ relu), store
    #pragma unroll
    for (int i = 0; i < 8; i++) {
        int gm = block_m + ty * 8 + i;
        if (gm < M) {
            #pragma unroll
            for (int j = 0; j < 8; j++) {
                float v = acc[i][j] + bias[tx * 8 + j];
                if (RELU) v = fmaxf(v, 0.f);
                C[(size_t)gm * 128 + tx * 8 + j] = v;
            }
        }
    }
}

// ---------------------------------------------------------------------------
// Pooling: batch is sorted. One block per 128 consecutive nodes; thread =
// feature column. Segmented local accumulation -> ~1-2 atomics/col/block.
// ---------------------------------------------------------------------------
__global__ void pool_kernel(const float* __restrict__ h, const int* __restrict__ batch,
                            float* __restrict__ out, float* __restrict__ cnt) {
    __shared__ int sb[128];
    const int b0 = blockIdx.x * 128;
    const int c = threadIdx.x;
    const int nrows = min(128, NN - b0);
    if (c < nrows) sb[c] = batch[b0 + c];
    __syncthreads();

    int cur = sb[0];
    float acc = 0.f;
    float cn = 0.f;
    for (int i = 0; i < nrows; i++) {
        int g = sb[i];
        if (g != cur) {
            atomicAdd(&out[cur * 128 + c], acc);
            if (c == 0) atomicAdd(&cnt[cur], cn);
            acc = 0.f; cn = 0.f; cur = g;
        }
        acc += h[(size_t)(b0 + i) * 128 + c];
        cn += 1.f;
    }
    atomicAdd(&out[cur * 128 + c], acc);
    if (c == 0) atomicAdd(&cnt[cur], cn);
}

__global__ void zero_kernel(float* __restrict__ out, float* __restrict__ cnt) {
    int i = blockIdx.x * blockDim.x + threadIdx.x;
    if (i < GG * HH) out[i] = 0.f;
    if (i < GG) cnt[i] = 0.f;
}

__global__ void div_kernel(float* __restrict__ out, const float* __restrict__ cnt) {
    int i = blockIdx.x * blockDim.x + threadIdx.x;
    if (i < GG * HH) out[i] /= fmaxf(cnt[i >> 7], 1.f);
}

// ---------------------------------------------------------------------------
// Launch
// ---------------------------------------------------------------------------
extern "C" void kernel_launch(void* const* d_in, const int* in_sizes, int n_in,
                              void* d_out, int out_size) {
    (void)in_sizes; (void)n_in; (void)out_size;

    const float* x          = (const float*)d_in[0];
    const int*   edge_index = (const int*)d_in[1];   // [2, E]: row0=src, row1=dst
    const int*   batch      = (const int*)d_in[2];
    const int*   e_src = edge_index;
    const int*   e_dst = edge_index + EE;
    float* out = (float*)d_out;

    void *ph, *pagg, *ptmp, *pcnt;
    cudaGetSymbolAddress(&ph,   g_h);
    cudaGetSymbolAddress(&pagg, g_agg);
    cudaGetSymbolAddress(&ptmp, g_tmp);
    cudaGetSymbolAddress(&pcnt, g_cnt);
    float* h   = (float*)ph;
    float* agg = (float*)pagg;
    float* tmp = (float*)ptmp;
    float* cnt = (float*)pcnt;

    const int n4 = NN * HH / 4;                       // 3,200,000
    const int copy_blocks    = (n4 + 255) / 256;
    const int scatter_blocks = (EE * 32 + 255) / 256; // 1 warp/edge
    const int gemm_blocks    = (NN + 127) / 128;      // 782

    const float* in = x;
    for (int l = 0; l < 3; l++) {
        const float* W1 = (const float*)d_in[3 + 4 * l + 0];
        const float* b1 = (const float*)d_in[3 + 4 * l + 1];
        const float* W2 = (const float*)d_in[3 + 4 * l + 2];
        const float* b2 = (const float*)d_in[3 + 4 * l + 3];

        copy_kernel<<<copy_blocks, 256>>>((const float4*)in, (float4*)agg, n4);
        scatter_kernel<<<scatter_blocks, 256>>>(in, e_src, e_dst, agg);
        gemm_kernel<true><<<gemm_blocks, 256>>>(agg, W1, b1, tmp, NN);
        gemm_kernel<false><<<gemm_blocks, 256>>>(tmp, W2, b2, h, NN);
        in = h;
    }

    zero_kernel<<<(GG * HH + 255) / 256, 256>>>(out, cnt);
    pool_kernel<<<(NN + 127) / 128, 128>>>(h, batch, out, cnt);
    div_kernel<<<(GG * HH + 255) / 256, 256>>>(out, cnt);
}

// round 2
// speedup vs baseline: 1.7226x; 1.7226x over previous
#include <cuda_runtime.h>
#include <cstddef>

#define NN 100000
#define EE 1600000
#define HH 128
#define GG 128

// Scratch in __device__ globals (allocation-free rule).
__device__ float g_h[(size_t)NN * HH];    // layer output
__device__ float g_agg[(size_t)NN * HH];  // aggregation buffer (x + sum_neighbors)
__device__ float g_tmp[(size_t)NN * HH];  // MLP intermediate
__device__ float g_cnt[GG];               // per-graph node counts

// Fire-and-forget vectorized global reduction (sm_90+).
__device__ __forceinline__ void red_add_v4(float* p, float4 v) {
    asm volatile("red.global.add.v4.f32 [%0], {%1,%2,%3,%4};"
                 :: "l"(p), "f"(v.x), "f"(v.y), "f"(v.z), "f"(v.w)
                 : "memory");
}

// ---------------------------------------------------------------------------
// copy: agg = src  (initializes with self term, scatter adds neighbors)
// ---------------------------------------------------------------------------
__global__ void copy_kernel(const float4* __restrict__ src, float4* __restrict__ dst, int n4) {
    int i = blockIdx.x * blockDim.x + threadIdx.x;
    if (i < n4) dst[i] = src[i];
}

// ---------------------------------------------------------------------------
// scatter: 2 edges per warp; 16 lanes per edge, each lane handles 8 floats
// (2 x float4). agg[dst] += h[src] via red.global.add.v4.f32 (no return).
// ---------------------------------------------------------------------------
__global__ __launch_bounds__(256)
void scatter_kernel(const float* __restrict__ h,
                    const int* __restrict__ src,
                    const int* __restrict__ dst,
                    float* __restrict__ agg) {
    int warp = (blockIdx.x * blockDim.x + threadIdx.x) >> 5;
    int lane = threadIdx.x & 31;
    int half = lane >> 4;           // which of 2 edges this lane serves
    int sub  = lane & 15;           // 16 lanes per edge
    int e = warp * 2 + half;
    if (e >= EE) return;
    int s = __ldg(src + e);
    int d = __ldg(dst + e);
    const float4* hp = reinterpret_cast<const float4*>(h + (size_t)s * HH) + sub;
    float*        ap = agg + (size_t)d * HH + sub * 4;
    float4 v0 = hp[0];
    float4 v1 = hp[16];
    red_add_v4(ap,      v0);
    red_add_v4(ap + 64, v1);
}

// ---------------------------------------------------------------------------
// SGEMM: C[M,128] = op(A[M,128] @ W[128,128] + bias), op = relu or identity
// Tile: BM=128, BN=128 (full), BK=16. 256 threads, 8x8 micro-tile each.
// ---------------------------------------------------------------------------
template <bool RELU>
__global__ __launch_bounds__(256, 2)
void gemm_kernel(const float* __restrict__ A, const float* __restrict__ W,
                 const float* __restrict__ bias, float* __restrict__ C, int M) {
    __shared__ float As[16][129];   // padded: transpose-store conflicts -> <=2-way
    __shared__ float Bs[16][128];

    const int block_m = blockIdx.x * 128;
    const int tid = threadIdx.x;
    const int tx = tid & 15;        // N-tile coord (8 cols each)
    const int ty = tid >> 4;        // M-tile coord (8 rows each)

    float acc[8][8];
    #pragma unroll
    for (int i = 0; i < 8; i++)
        #pragma unroll
        for (int j = 0; j < 8; j++) acc[i][j] = 0.f;

    for (int k0 = 0; k0 < 128; k0 += 16) {
        // Load A tile 128x16 (2048 elems, 8 per thread, row-major coalesced)
        #pragma unroll
        for (int i = 0; i < 8; i++) {
            int e = tid + i * 256;
            int m = e >> 4;
            int k = e & 15;
            int gm = block_m + m;
            As[k][m] = (gm < M) ? A[(size_t)gm * 128 + k0 + k] : 0.f;
        }
        // Load B tile 16x128 (coalesced, conflict-free)
        #pragma unroll
        for (int i = 0; i < 8; i++) {
            int e = tid + i * 256;
            int k = e >> 7;
            int n = e & 127;
            Bs[k][n] = W[(size_t)(k0 + k) * 128 + n];
        }
        __syncthreads();

        #pragma unroll
        for (int k = 0; k < 16; k++) {
            float a[8], b[8];
            #pragma unroll
            for (int i = 0; i < 8; i++) a[i] = As[k][ty * 8 + i];
            #pragma unroll
            for (int j = 0; j < 8; j++) b[j] = Bs[k][tx * 8 + j];
            #pragma unroll
            for (int i = 0; i < 8; i++)
                #pragma unroll
                for (int j = 0; j < 8; j++)
                    acc[i][j] = fmaf(a[i], b[j], acc[i][j]);
        }
        __syncthreads();
    }

    // Epilogue: bias (+ relu), store
    #pragma unroll
    for (int i = 0; i < 8; i++) {
        int gm = block_m + ty * 8 + i;
        if (gm < M) {
            #pragma unroll
            for (int j = 0; j < 8; j++) {
                float v = acc[i][j] + bias[tx * 8 + j];
                if (RELU) v = fmaxf(v, 0.f);
                C[(size_t)gm * 128 + tx * 8 + j] = v;
            }
        }
    }
}

// ---------------------------------------------------------------------------
// Pooling: batch is sorted. One block per 128 consecutive nodes; thread =
// feature column. Segmented local accumulation -> ~1-2 atomics/col/block.
// ---------------------------------------------------------------------------
__global__ void pool_kernel(const float* __restrict__ h, const int* __restrict__ batch,
                            float* __restrict__ out, float* __restrict__ cnt) {
    __shared__ int sb[128];
    const int b0 = blockIdx.x * 128;
    const int c = threadIdx.x;
    const int nrows = min(128, NN - b0);
    if (c < nrows) sb[c] = batch[b0 + c];
    __syncthreads();

    int cur = sb[0];
    float acc = 0.f;
    float cn = 0.f;
    for (int i = 0; i < nrows; i++) {
        int g = sb[i];
        if (g != cur) {
            atomicAdd(&out[cur * 128 + c], acc);
            if (c == 0) atomicAdd(&cnt[cur], cn);
            acc = 0.f; cn = 0.f; cur = g;
        }
        acc += h[(size_t)(b0 + i) * 128 + c];
        cn += 1.f;
    }
    atomicAdd(&out[cur * 128 + c], acc);
    if (c == 0) atomicAdd(&cnt[cur], cn);
}

__global__ void zero_kernel(float* __restrict__ out, float* __restrict__ cnt) {
    int i = blockIdx.x * blockDim.x + threadIdx.x;
    if (i < GG * HH) out[i] = 0.f;
    if (i < GG) cnt[i] = 0.f;
}

__global__ void div_kernel(float* __restrict__ out, const float* __restrict__ cnt) {
    int i = blockIdx.x * blockDim.x + threadIdx.x;
    if (i < GG * HH) out[i] /= fmaxf(cnt[i >> 7], 1.f);
}

// ---------------------------------------------------------------------------
// Launch
// ---------------------------------------------------------------------------
extern "C" void kernel_launch(void* const* d_in, const int* in_sizes, int n_in,
                              void* d_out, int out_size) {
    (void)in_sizes; (void)n_in; (void)out_size;

    const float* x          = (const float*)d_in[0];
    const int*   edge_index = (const int*)d_in[1];   // [2, E]: row0=src, row1=dst
    const int*   batch      = (const int*)d_in[2];
    const int*   e_src = edge_index;
    const int*   e_dst = edge_index + EE;
    float* out = (float*)d_out;

    void *ph, *pagg, *ptmp, *pcnt;
    cudaGetSymbolAddress(&ph,   g_h);
    cudaGetSymbolAddress(&pagg, g_agg);
    cudaGetSymbolAddress(&ptmp, g_tmp);
    cudaGetSymbolAddress(&pcnt, g_cnt);
    float* h   = (float*)ph;
    float* agg = (float*)pagg;
    float* tmp = (float*)ptmp;
    float* cnt = (float*)pcnt;

    const int n4 = NN * HH / 4;                       // 3,200,000
    const int copy_blocks    = (n4 + 255) / 256;
    const int scatter_warps  = (EE + 1) / 2;          // 2 edges per warp
    const int scatter_blocks = (scatter_warps * 32 + 255) / 256;
    const int gemm_blocks    = (NN + 127) / 128;      // 782

    const float* in = x;
    for (int l = 0; l < 3; l++) {
        const float* W1 = (const float*)d_in[3 + 4 * l + 0];
        const float* b1 = (const float*)d_in[3 + 4 * l + 1];
        const float* W2 = (const float*)d_in[3 + 4 * l + 2];
        const float* b2 = (const float*)d_in[3 + 4 * l + 3];

        copy_kernel<<<copy_blocks, 256>>>((const float4*)in, (float4*)agg, n4);
        scatter_kernel<<<scatter_blocks, 256>>>(in, e_src, e_dst, agg);
        gemm_kernel<true><<<gemm_blocks, 256>>>(agg, W1, b1, tmp, NN);
        gemm_kernel<false><<<gemm_blocks, 256>>>(tmp, W2, b2, h, NN);
        in = h;
    }

    zero_kernel<<<(GG * HH + 255) / 256, 256>>>(out, cnt);
    pool_kernel<<<(NN + 127) / 128, 128>>>(h, batch, out, cnt);
    div_kernel<<<(GG * HH + 255) / 256, 256>>>(out, cnt);
}

// round 4
// speedup vs baseline: 2.4325x; 1.4121x over previous
#include <cuda_runtime.h>
#include <cuda_bf16.h>
#include <cstdint>
#include <cstddef>

#define NN 100000
#define EE 1600000
#define HH 128
#define GG 128

// ---------------------------------------------------------------------------
// Scratch (__device__ globals; allocation-free rule)
// ---------------------------------------------------------------------------
__device__ float g_h[(size_t)NN * HH];            // layer output (fp32)
__device__ float g_agg[(size_t)NN * HH];          // x + sum_neighbors (fp32)
__device__ __nv_bfloat16 g_tH[(size_t)NN * HH];   // MLP mid hi split
__device__ __nv_bfloat16 g_tL[(size_t)NN * HH];   // MLP mid lo split
__device__ __nv_bfloat16 g_wH[6 * HH * HH];       // transposed weights hi ([n][k])
__device__ __nv_bfloat16 g_wL[6 * HH * HH];       // transposed weights lo
__device__ float g_cnt[GG];

// ---------------------------------------------------------------------------
// helpers
// ---------------------------------------------------------------------------
__device__ __forceinline__ uint32_t smem_u32(const void* p) {
    uint32_t a;
    asm("{ .reg .u64 t; cvta.to.shared.u64 t, %1; cvt.u32.u64 %0, t; }" : "=r"(a) : "l"(p));
    return a;
}

__device__ __forceinline__ void ldsm4(uint32_t* r, uint32_t addr) {
    asm volatile("ldmatrix.sync.aligned.m8n8.x4.shared.b16 {%0,%1,%2,%3}, [%4];"
                 : "=r"(r[0]), "=r"(r[1]), "=r"(r[2]), "=r"(r[3]) : "r"(addr));
}

__device__ __forceinline__ void mma16816(float* c, const uint32_t* a, uint32_t b0, uint32_t b1) {
    asm volatile("mma.sync.aligned.m16n8k16.row.col.f32.bf16.bf16.f32 "
                 "{%0,%1,%2,%3}, {%4,%5,%6,%7}, {%8,%9}, {%0,%1,%2,%3};"
                 : "+f"(c[0]), "+f"(c[1]), "+f"(c[2]), "+f"(c[3])
                 : "r"(a[0]), "r"(a[1]), "r"(a[2]), "r"(a[3]), "r"(b0), "r"(b1));
}

__device__ __forceinline__ uint32_t pk(__nv_bfloat16 a, __nv_bfloat16 b) {
    __nv_bfloat162 t(a, b);
    return *reinterpret_cast<uint32_t*>(&t);
}

// ---------------------------------------------------------------------------
// copy: agg = src
// ---------------------------------------------------------------------------
__global__ void copy_kernel(const float4* __restrict__ src, float4* __restrict__ dst, int n4) {
    int i = blockIdx.x * blockDim.x + threadIdx.x;
    if (i < n4) dst[i] = src[i];
}

// ---------------------------------------------------------------------------
// scatter: 2 edges per warp, red.global.add.v4.f32 (fire-and-forget)
// ---------------------------------------------------------------------------
__device__ __forceinline__ void red_add_v4(float* p, float4 v) {
    asm volatile("red.global.add.v4.f32 [%0], {%1,%2,%3,%4};"
                 :: "l"(p), "f"(v.x), "f"(v.y), "f"(v.z), "f"(v.w) : "memory");
}

__global__ __launch_bounds__(256)
void scatter_kernel(const float* __restrict__ h,
                    const int* __restrict__ src,
                    const int* __restrict__ dst,
                    float* __restrict__ agg) {
    int warp = (blockIdx.x * blockDim.x + threadIdx.x) >> 5;
    int lane = threadIdx.x & 31;
    int half = lane >> 4;
    int sub  = lane & 15;
    int e = warp * 2 + half;
    if (e >= EE) return;
    int s = __ldg(src + e);
    int d = __ldg(dst + e);
    const float4* hp = reinterpret_cast<const float4*>(h + (size_t)s * HH) + sub;
    float*        ap = agg + (size_t)d * HH + sub * 4;
    float4 v0 = hp[0];
    float4 v1 = hp[16];
    red_add_v4(ap,      v0);
    red_add_v4(ap + 64, v1);
}

// ---------------------------------------------------------------------------
// Weights: transpose + split. out[m][n][k] = W_m[k][n]
// ---------------------------------------------------------------------------
__global__ void wconv_kernel(const float* __restrict__ W0, const float* __restrict__ W1,
                             const float* __restrict__ W2, const float* __restrict__ W3,
                             const float* __restrict__ W4, const float* __restrict__ W5,
                             __nv_bfloat16* __restrict__ wh, __nv_bfloat16* __restrict__ wl) {
    int i = blockIdx.x * blockDim.x + threadIdx.x;
    if (i >= 6 * HH * HH) return;
    int m = i / (HH * HH);
    int r = i % (HH * HH);
    int n = r / HH;
    int k = r % HH;
    const float* W = (m == 0) ? W0 : (m == 1) ? W1 : (m == 2) ? W2
                   : (m == 3) ? W3 : (m == 4) ? W4 : W5;
    float v = W[k * HH + n];
    __nv_bfloat16 h = __float2bfloat16(v);
    wh[i] = h;
    wl[i] = __float2bfloat16(v - __bfloat162float(h));
}

// ---------------------------------------------------------------------------
// mma.sync GEMM: C[M,128] = op(A @ W + bias), split-precision 3-pass.
//   SPLITIN=false: A read as fp32 (converted to hi/lo during staging)
//   SPLITIN=true:  A read as bf16 hi/lo pair
//   SPLITOUT=true: C written as bf16 hi/lo pair; else fp32
// Tile: 128x128x128. 256 threads, warp = 16 rows x 128 cols.
// Smem pitch 272B -> conflict-free ldmatrix.
// ---------------------------------------------------------------------------
#define PITCH 272
#define S_AH 0
#define S_AL 34816
#define S_BH 69632
#define S_BL 104448
#define GEMM_SMEM 139264

template <bool RELU, bool SPLITIN, bool SPLITOUT>
__global__ __launch_bounds__(256)
void gemm_mma(const float* __restrict__ Af,
              const __nv_bfloat16* __restrict__ Ah, const __nv_bfloat16* __restrict__ Al,
              const __nv_bfloat16* __restrict__ Bh, const __nv_bfloat16* __restrict__ Bl,
              const float* __restrict__ bias,
              float* __restrict__ Cf,
              __nv_bfloat16* __restrict__ Ch, __nv_bfloat16* __restrict__ Cl,
              int M) {
    extern __shared__ __align__(16) char smem[];
    const uint32_t sb = smem_u32(smem);
    const int tid = threadIdx.x;
    const int wid = tid >> 5, lane = tid & 31;
    const int block_m = blockIdx.x * 128;

    // ---- stage tiles ----
    #pragma unroll
    for (int it = 0; it < 8; it++) {
        int idx = it * 256 + tid;       // 0..2047
        int row = idx >> 4;             // 0..127
        int c   = idx & 15;             // 16B chunk (8 bf16 / 8 floats' worth)
        // B (weights, [n][k] bf16)
        uint4 bh = *reinterpret_cast<const uint4*>(Bh + (size_t)row * HH + c * 8);
        uint4 bl = *reinterpret_cast<const uint4*>(Bl + (size_t)row * HH + c * 8);
        *reinterpret_cast<uint4*>(smem + S_BH + row * PITCH + c * 16) = bh;
        *reinterpret_cast<uint4*>(smem + S_BL + row * PITCH + c * 16) = bl;
        // A
        int gm = block_m + row;
        uint4 vh = make_uint4(0, 0, 0, 0), vl = vh;
        if (SPLITIN) {
            if (gm < M) {
                vh = *reinterpret_cast<const uint4*>(Ah + (size_t)gm * HH + c * 8);
                vl = *reinterpret_cast<const uint4*>(Al + (size_t)gm * HH + c * 8);
            }
        } else {
            if (gm < M) {
                float4 f0 = *reinterpret_cast<const float4*>(Af + (size_t)gm * HH + c * 8);
                float4 f1 = *reinterpret_cast<const float4*>(Af + (size_t)gm * HH + c * 8 + 4);
                float fv[8] = {f0.x, f0.y, f0.z, f0.w, f1.x, f1.y, f1.z, f1.w};
                uint32_t hp_[4], lp_[4];
                #pragma unroll
                for (int j = 0; j < 4; j++) {
                    __nv_bfloat16 h0 = __float2bfloat16(fv[2 * j]);
                    __nv_bfloat16 h1 = __float2bfloat16(fv[2 * j + 1]);
                    __nv_bfloat16 l0 = __float2bfloat16(fv[2 * j] - __bfloat162float(h0));
                    __nv_bfloat16 l1 = __float2bfloat16(fv[2 * j + 1] - __bfloat162float(h1));
                    hp_[j] = pk(h0, h1);
                    lp_[j] = pk(l0, l1);
                }
                vh = make_uint4(hp_[0], hp_[1], hp_[2], hp_[3]);
                vl = make_uint4(lp_[0], lp_[1], lp_[2], lp_[3]);
            }
        }
        *reinterpret_cast<uint4*>(smem + S_AH + row * PITCH + c * 16) = vh;
        *reinterpret_cast<uint4*>(smem + S_AL + row * PITCH + c * 16) = vl;
    }
    __syncthreads();

    // ---- mainloop ----
    // ldmatrix lane pattern: matrices (rows0-7,k0) (rows8-15,k0) (rows0-7,k8) (rows8-15,k8)
    const int arow = (lane & 7) | (lane & 8);
    const int akc  = (lane & 16) >> 1;        // 0 or 8 (k offset)
    const uint32_t aoffH = sb + S_AH + (wid * 16 + arow) * PITCH + akc * 2;
    const uint32_t aoffL = aoffH + (S_AL - S_AH);
    const uint32_t boffH = sb + S_BH + arow * PITCH + akc * 2;
    const uint32_t boffL = boffH + (S_BL - S_BH);

    float acc[16][4];
    #pragma unroll
    for (int i = 0; i < 16; i++)
        #pragma unroll
        for (int j = 0; j < 4; j++) acc[i][j] = 0.f;

    #pragma unroll
    for (int ks = 0; ks < 8; ks++) {
        uint32_t aH[4], aL[4];
        ldsm4(aH, aoffH + ks * 32);
        ldsm4(aL, aoffL + ks * 32);
        #pragma unroll
        for (int np = 0; np < 8; np++) {
            uint32_t bh[4], bl[4];
            ldsm4(bh, boffH + np * (16 * PITCH) + ks * 32);
            ldsm4(bl, boffL + np * (16 * PITCH) + ks * 32);
            float* c0 = acc[2 * np];
            float* c1 = acc[2 * np + 1];
            mma16816(c0, aH, bh[0], bh[2]);
            mma16816(c0, aL, bh[0], bh[2]);
            mma16816(c0, aH, bl[0], bl[2]);
            mma16816(c1, aH, bh[1], bh[3]);
            mma16816(c1, aL, bh[1], bh[3]);
            mma16816(c1, aH, bl[1], bl[3]);
        }
    }

    // ---- epilogue ----
    // thread t: rows r0 = base + t/4, r1 = r0 + 8; cols (t%4)*2 + nt*8
    const int quad = lane >> 2;
    const int qcol = (lane & 3) * 2;
    const int r0 = block_m + wid * 16 + quad;
    const int r1 = r0 + 8;
    #pragma unroll
    for (int nt = 0; nt < 16; nt++) {
        int col = nt * 8 + qcol;
        float b0 = __ldg(bias + col), b1 = __ldg(bias + col + 1);
        float v00 = acc[nt][0] + b0, v01 = acc[nt][1] + b1;
        float v10 = acc[nt][2] + b0, v11 = acc[nt][3] + b1;
        if (RELU) {
            v00 = fmaxf(v00, 0.f); v01 = fmaxf(v01, 0.f);
            v10 = fmaxf(v10, 0.f); v11 = fmaxf(v11, 0.f);
        }
        if (SPLITOUT) {
            if (r0 < M) {
                __nv_bfloat16 h0 = __float2bfloat16(v00), h1 = __float2bfloat16(v01);
                *reinterpret_cast<uint32_t*>(Ch + (size_t)r0 * HH + col) = pk(h0, h1);
                *reinterpret_cast<uint32_t*>(Cl + (size_t)r0 * HH + col) =
                    pk(__float2bfloat16(v00 - __bfloat162float(h0)),
                       __float2bfloat16(v01 - __bfloat162float(h1)));
            }
            if (r1 < M) {
                __nv_bfloat16 h0 = __float2bfloat16(v10), h1 = __float2bfloat16(v11);
                *reinterpret_cast<uint32_t*>(Ch + (size_t)r1 * HH + col) = pk(h0, h1);
                *reinterpret_cast<uint32_t*>(Cl + (size_t)r1 * HH + col) =
                    pk(__float2bfloat16(v10 - __bfloat162float(h0)),
                       __float2bfloat16(v11 - __bfloat162float(h1)));
            }
        } else {
            if (r0 < M) *reinterpret_cast<float2*>(Cf + (size_t)r0 * HH + col) = make_float2(v00, v01);
            if (r1 < M) *reinterpret_cast<float2*>(Cf + (size_t)r1 * HH + col) = make_float2(v10, v11);
        }
    }
}

// ---------------------------------------------------------------------------
// Pooling (batch sorted): block = 128 nodes, thread = feature column.
// ---------------------------------------------------------------------------
__global__ void pool_kernel(const float* __restrict__ h, const int* __restrict__ batch,
                            float* __restrict__ out, float* __restrict__ cnt) {
    __shared__ int sbv[128];
    const int b0 = blockIdx.x * 128;
    const int c = threadIdx.x;
    const int nrows = min(128, NN - b0);
    if (c < nrows) sbv[c] = batch[b0 + c];
    __syncthreads();

    int cur = sbv[0];
    float acc = 0.f, cn = 0.f;
    for (int i = 0; i < nrows; i++) {
        int g = sbv[i];
        if (g != cur) {
            atomicAdd(&out[cur * 128 + c], acc);
            if (c == 0) atomicAdd(&cnt[cur], cn);
            acc = 0.f; cn = 0.f; cur = g;
        }
        acc += h[(size_t)(b0 + i) * 128 + c];
        cn += 1.f;
    }
    atomicAdd(&out[cur * 128 + c], acc);
    if (c == 0) atomicAdd(&cnt[cur], cn);
}

__global__ void zero_kernel(float* __restrict__ out, float* __restrict__ cnt) {
    int i = blockIdx.x * blockDim.x + threadIdx.x;
    if (i < GG * HH) out[i] = 0.f;
    if (i < GG) cnt[i] = 0.f;
}

__global__ void div_kernel(float* __restrict__ out, const float* __restrict__ cnt) {
    int i = blockIdx.x * blockDim.x + threadIdx.x;
    if (i < GG * HH) out[i] /= fmaxf(cnt[i >> 7], 1.f);
}

// ---------------------------------------------------------------------------
// Launch
// ---------------------------------------------------------------------------
extern "C" void kernel_launch(void* const* d_in, const int* in_sizes, int n_in,
                              void* d_out, int out_size) {
    (void)in_sizes; (void)n_in; (void)out_size;

    const float* x          = (const float*)d_in[0];
    const int*   edge_index = (const int*)d_in[1];
    const int*   batch      = (const int*)d_in[2];
    const int*   e_src = edge_index;
    const int*   e_dst = edge_index + EE;
    float* out = (float*)d_out;

    void *ph, *pagg, *ptH, *ptL, *pwH, *pwL, *pcnt;
    cudaGetSymbolAddress(&ph,   g_h);
    cudaGetSymbolAddress(&pagg, g_agg);
    cudaGetSymbolAddress(&ptH,  g_tH);
    cudaGetSymbolAddress(&ptL,  g_tL);
    cudaGetSymbolAddress(&pwH,  g_wH);
    cudaGetSymbolAddress(&pwL,  g_wL);
    cudaGetSymbolAddress(&pcnt, g_cnt);
    float* h   = (float*)ph;
    float* agg = (float*)pagg;
    __nv_bfloat16* tH = (__nv_bfloat16*)ptH;
    __nv_bfloat16* tL = (__nv_bfloat16*)ptL;
    __nv_bfloat16* wH = (__nv_bfloat16*)pwH;
    __nv_bfloat16* wL = (__nv_bfloat16*)pwL;
    float* cnt = (float*)pcnt;

    cudaFuncSetAttribute(gemm_mma<true, false, true>,
                         cudaFuncAttributeMaxDynamicSharedMemorySize, GEMM_SMEM);
    cudaFuncSetAttribute(gemm_mma<false, true, false>,
                         cudaFuncAttributeMaxDynamicSharedMemorySize, GEMM_SMEM);

    const int n4 = NN * HH / 4;
    const int copy_blocks    = (n4 + 255) / 256;
    const int scatter_warps  = (EE + 1) / 2;
    const int scatter_blocks = (scatter_warps * 32 + 255) / 256;
    const int gemm_blocks    = (NN + 127) / 128;   // 782
    const int wconv_blocks   = (6 * HH * HH + 255) / 256;

    wconv_kernel<<<wconv_blocks, 256>>>((const float*)d_in[3], (const float*)d_in[5],
                                        (const float*)d_in[7], (const float*)d_in[9],
                                        (const float*)d_in[11], (const float*)d_in[13],
                                        wH, wL);

    const float* in = x;
    for (int l = 0; l < 3; l++) {
        const float* b1 = (const float*)d_in[3 + 4 * l + 1];
        const float* b2 = (const float*)d_in[3 + 4 * l + 3];
        __nv_bfloat16* w1H = wH + (size_t)(2 * l) * HH * HH;
        __nv_bfloat16* w1L = wL + (size_t)(2 * l) * HH * HH;
        __nv_bfloat16* w2H = wH + (size_t)(2 * l + 1) * HH * HH;
        __nv_bfloat16* w2L = wL + (size_t)(2 * l + 1) * HH * HH;

        copy_kernel<<<copy_blocks, 256>>>((const float4*)in, (float4*)agg, n4);
        scatter_kernel<<<scatter_blocks, 256>>>(in, e_src, e_dst, agg);
        // GEMM1: fp32 agg in -> relu -> bf16 split out
        gemm_mma<true, false, true><<<gemm_blocks, 256, GEMM_SMEM>>>(
            agg, nullptr, nullptr, w1H, w1L, b1, nullptr, tH, tL, NN);
        // GEMM2: bf16 split in -> fp32 out
        gemm_mma<false, true, false><<<gemm_blocks, 256, GEMM_SMEM>>>(
            nullptr, tH, tL, w2H, w2L, b2, h, nullptr, nullptr, NN);
        in = h;
    }

    zero_kernel<<<(GG * HH + 255) / 256, 256>>>(out, cnt);
    pool_kernel<<<(NN + 127) / 128, 128>>>(h, batch, out, cnt);
    div_kernel<<<(GG * HH + 255) / 256, 256>>>(out, cnt);
}

// round 5
// speedup vs baseline: 2.8808x; 1.1843x over previous
#include <cuda_runtime.h>
#include <cuda_bf16.h>
#include <cstdint>
#include <cstddef>

#define NN 100000
#define EE 1600000
#define HH 128
#define GG 128

// ---------------------------------------------------------------------------
// Scratch (__device__ globals; allocation-free rule)
// ---------------------------------------------------------------------------
__device__ float g_h[(size_t)NN * HH];            // layer output (fp32)
__device__ float g_agg[(size_t)NN * HH];          // sum_neighbors (fp32), zeroed per layer
__device__ __nv_bfloat16 g_wH[6 * HH * HH];       // transposed weights hi ([n][k])
__device__ __nv_bfloat16 g_wL[6 * HH * HH];       // transposed weights lo
__device__ float g_cnt[GG];

// ---------------------------------------------------------------------------
// helpers
// ---------------------------------------------------------------------------
__device__ __forceinline__ uint32_t smem_u32(const void* p) {
    uint32_t a;
    asm("{ .reg .u64 t; cvta.to.shared.u64 t, %1; cvt.u32.u64 %0, t; }" : "=r"(a) : "l"(p));
    return a;
}

__device__ __forceinline__ void ldsm4(uint32_t* r, uint32_t addr) {
    asm volatile("ldmatrix.sync.aligned.m8n8.x4.shared.b16 {%0,%1,%2,%3}, [%4];"
                 : "=r"(r[0]), "=r"(r[1]), "=r"(r[2]), "=r"(r[3]) : "r"(addr));
}

__device__ __forceinline__ void mma16816(float* c, const uint32_t* a, uint32_t b0, uint32_t b1) {
    asm volatile("mma.sync.aligned.m16n8k16.row.col.f32.bf16.bf16.f32 "
                 "{%0,%1,%2,%3}, {%4,%5,%6,%7}, {%8,%9}, {%0,%1,%2,%3};"
                 : "+f"(c[0]), "+f"(c[1]), "+f"(c[2]), "+f"(c[3])
                 : "r"(a[0]), "r"(a[1]), "r"(a[2]), "r"(a[3]), "r"(b0), "r"(b1));
}

__device__ __forceinline__ uint32_t pk(__nv_bfloat16 a, __nv_bfloat16 b) {
    __nv_bfloat162 t(a, b);
    return *reinterpret_cast<uint32_t*>(&t);
}

__device__ __forceinline__ uint32_t split_hi(float v0, float v1, uint32_t& lo) {
    __nv_bfloat16 h0 = __float2bfloat16(v0), h1 = __float2bfloat16(v1);
    lo = pk(__float2bfloat16(v0 - __bfloat162float(h0)),
            __float2bfloat16(v1 - __bfloat162float(h1)));
    return pk(h0, h1);
}

// ---------------------------------------------------------------------------
// zero agg
// ---------------------------------------------------------------------------
__global__ void zero_agg_kernel(float4* __restrict__ agg, int n4) {
    int i = blockIdx.x * blockDim.x + threadIdx.x;
    if (i < n4) agg[i] = make_float4(0.f, 0.f, 0.f, 0.f);
}

// ---------------------------------------------------------------------------
// scatter: 2 edges per warp, red.global.add.v4.f32 (fire-and-forget)
// ---------------------------------------------------------------------------
__device__ __forceinline__ void red_add_v4(float* p, float4 v) {
    asm volatile("red.global.add.v4.f32 [%0], {%1,%2,%3,%4};"
                 :: "l"(p), "f"(v.x), "f"(v.y), "f"(v.z), "f"(v.w) : "memory");
}

__global__ __launch_bounds__(256)
void scatter_kernel(const float* __restrict__ h,
                    const int* __restrict__ src,
                    const int* __restrict__ dst,
                    float* __restrict__ agg) {
    int warp = (blockIdx.x * blockDim.x + threadIdx.x) >> 5;
    int lane = threadIdx.x & 31;
    int half = lane >> 4;
    int sub  = lane & 15;
    int e = warp * 2 + half;
    if (e >= EE) return;
    int s = __ldg(src + e);
    int d = __ldg(dst + e);
    const float4* hp = reinterpret_cast<const float4*>(h + (size_t)s * HH) + sub;
    float*        ap = agg + (size_t)d * HH + sub * 4;
    float4 v0 = hp[0];
    float4 v1 = hp[16];
    red_add_v4(ap,      v0);
    red_add_v4(ap + 64, v1);
}

// ---------------------------------------------------------------------------
// Weights: transpose + split. out[m][n][k] = W_m[k][n]
// ---------------------------------------------------------------------------
__global__ void wconv_kernel(const float* __restrict__ W0, const float* __restrict__ W1,
                             const float* __restrict__ W2, const float* __restrict__ W3,
                             const float* __restrict__ W4, const float* __restrict__ W5,
                             __nv_bfloat16* __restrict__ wh, __nv_bfloat16* __restrict__ wl) {
    int i = blockIdx.x * blockDim.x + threadIdx.x;
    if (i >= 6 * HH * HH) return;
    int m = i / (HH * HH);
    int r = i % (HH * HH);
    int n = r / HH;
    int k = r % HH;
    const float* W = (m == 0) ? W0 : (m == 1) ? W1 : (m == 2) ? W2
                   : (m == 3) ? W3 : (m == 4) ? W4 : W5;
    float v = W[k * HH + n];
    __nv_bfloat16 h = __float2bfloat16(v);
    wh[i] = h;
    wl[i] = __float2bfloat16(v - __bfloat162float(h));
}

// ---------------------------------------------------------------------------
// Fused MLP: out[M,128] = relu(A @ W1 + b1) @ W2 + b2,  A = in + agg (fp32)
// Split-precision 3-pass bf16 mma.sync. M-tile 64, 256 threads (8 warps:
// 4 row-groups x 2 col-halves). Smem 102KB -> 2 CTAs/SM.
// ---------------------------------------------------------------------------
#define PITCH 272
#define S_AH 0
#define S_AL (64 * PITCH)            // 17408
#define S_WH (2 * 64 * PITCH)        // 34816
#define S_WL (S_WH + 128 * PITCH)    // 69632
#define FUSED_SMEM (S_WL + 128 * PITCH)  // 104448

__global__ __launch_bounds__(256, 2)
void fused_mlp(const float* __restrict__ In, const float* __restrict__ Agg,
               const __nv_bfloat16* __restrict__ W1h, const __nv_bfloat16* __restrict__ W1l,
               const __nv_bfloat16* __restrict__ W2h, const __nv_bfloat16* __restrict__ W2l,
               const float* __restrict__ bias1, const float* __restrict__ bias2,
               float* __restrict__ Out, int M) {
    extern __shared__ __align__(16) char smem[];
    const uint32_t sb = smem_u32(smem);
    const int tid = threadIdx.x;
    const int wid = tid >> 5, lane = tid & 31;
    const int block_m = blockIdx.x * 64;

    // ---- stage A = in + agg (fp32 -> hi/lo bf16) : 64 rows x 16 chunks ----
    #pragma unroll
    for (int it = 0; it < 4; it++) {
        int idx = it * 256 + tid;       // 0..1023
        int row = idx >> 4;             // 0..63
        int c   = idx & 15;
        int gm  = block_m + row;
        uint4 vh = make_uint4(0, 0, 0, 0), vl = vh;
        if (gm < M) {
            const float* pi = In  + (size_t)gm * HH + c * 8;
            const float* pa = Agg + (size_t)gm * HH + c * 8;
            float4 i0 = *reinterpret_cast<const float4*>(pi);
            float4 i1 = *reinterpret_cast<const float4*>(pi + 4);
            float4 a0 = *reinterpret_cast<const float4*>(pa);
            float4 a1 = *reinterpret_cast<const float4*>(pa + 4);
            float fv[8] = {i0.x + a0.x, i0.y + a0.y, i0.z + a0.z, i0.w + a0.w,
                           i1.x + a1.x, i1.y + a1.y, i1.z + a1.z, i1.w + a1.w};
            uint32_t hp_[4], lp_[4];
            #pragma unroll
            for (int j = 0; j < 4; j++) hp_[j] = split_hi(fv[2 * j], fv[2 * j + 1], lp_[j]);
            vh = make_uint4(hp_[0], hp_[1], hp_[2], hp_[3]);
            vl = make_uint4(lp_[0], lp_[1], lp_[2], lp_[3]);
        }
        *reinterpret_cast<uint4*>(smem + S_AH + row * PITCH + c * 16) = vh;
        *reinterpret_cast<uint4*>(smem + S_AL + row * PITCH + c * 16) = vl;
    }
    // ---- stage W1 (hi/lo) : 128 rows x 16 chunks ----
    #pragma unroll
    for (int it = 0; it < 8; it++) {
        int idx = it * 256 + tid;       // 0..2047
        int row = idx >> 4;
        int c   = idx & 15;
        uint4 bh = *reinterpret_cast<const uint4*>(W1h + (size_t)row * HH + c * 8);
        uint4 bl = *reinterpret_cast<const uint4*>(W1l + (size_t)row * HH + c * 8);
        *reinterpret_cast<uint4*>(smem + S_WH + row * PITCH + c * 16) = bh;
        *reinterpret_cast<uint4*>(smem + S_WL + row * PITCH + c * 16) = bl;
    }
    __syncthreads();

    // ---- warp coords ----
    const int wr = wid >> 1;            // row group (16 rows)
    const int wc = wid & 1;             // col half (64 cols)
    const int arow = lane & 15;
    const int akc  = (lane & 16) >> 1;  // 0 or 8
    const uint32_t aHb = sb + S_AH + (wr * 16 + arow) * PITCH + akc * 2;
    const uint32_t aLb = aHb + (S_AL - S_AH);
    const uint32_t bHb = sb + S_WH + (wc * 64 + arow) * PITCH + akc * 2;
    const uint32_t bLb = bHb + (S_WL - S_WH);
    const int quad = lane >> 2;
    const int qc   = (lane & 3) * 2;

    float acc[8][4];

    // ================= GEMM 1 =================
    #pragma unroll
    for (int i = 0; i < 8; i++)
        #pragma unroll
        for (int j = 0; j < 4; j++) acc[i][j] = 0.f;

    #pragma unroll
    for (int ks = 0; ks < 8; ks++) {
        uint32_t aH[4], aL[4];
        ldsm4(aH, aHb + ks * 32);
        ldsm4(aL, aLb + ks * 32);
        #pragma unroll
        for (int np = 0; np < 4; np++) {
            uint32_t bh[4], bl[4];
            ldsm4(bh, bHb + np * (16 * PITCH) + ks * 32);
            ldsm4(bl, bLb + np * (16 * PITCH) + ks * 32);
            float* c0 = acc[2 * np];
            float* c1 = acc[2 * np + 1];
            mma16816(c0, aH, bh[0], bh[2]);
            mma16816(c0, aL, bh[0], bh[2]);
            mma16816(c0, aH, bl[0], bl[2]);
            mma16816(c1, aH, bh[1], bh[3]);
            mma16816(c1, aL, bh[1], bh[3]);
            mma16816(c1, aH, bl[1], bl[3]);
        }
    }
    __syncthreads();   // everyone done reading A + W1 smem

    // ---- epilogue 1: relu(acc + b1) -> hi/lo split -> overwrite A smem ----
    {
        const int lr0 = wr * 16 + quad;
        #pragma unroll
        for (int np = 0; np < 4; np++) {
            #pragma unroll
            for (int s = 0; s < 2; s++) {
                int nt = 2 * np + s;
                int col = wc * 64 + np * 16 + s * 8 + qc;
                float b0 = __ldg(bias1 + col), b1v = __ldg(bias1 + col + 1);
                float v00 = fmaxf(acc[nt][0] + b0, 0.f);
                float v01 = fmaxf(acc[nt][1] + b1v, 0.f);
                float v10 = fmaxf(acc[nt][2] + b0, 0.f);
                float v11 = fmaxf(acc[nt][3] + b1v, 0.f);
                uint32_t lo0, lo1;
                uint32_t hi0 = split_hi(v00, v01, lo0);
                uint32_t hi1 = split_hi(v10, v11, lo1);
                *reinterpret_cast<uint32_t*>(smem + S_AH + lr0 * PITCH + col * 2) = hi0;
                *reinterpret_cast<uint32_t*>(smem + S_AL + lr0 * PITCH + col * 2) = lo0;
                *reinterpret_cast<uint32_t*>(smem + S_AH + (lr0 + 8) * PITCH + col * 2) = hi1;
                *reinterpret_cast<uint32_t*>(smem + S_AL + (lr0 + 8) * PITCH + col * 2) = lo1;
            }
        }
    }
    // ---- stage W2 over the W region ----
    #pragma unroll
    for (int it = 0; it < 8; it++) {
        int idx = it * 256 + tid;
        int row = idx >> 4;
        int c   = idx & 15;
        uint4 bh = *reinterpret_cast<const uint4*>(W2h + (size_t)row * HH + c * 8);
        uint4 bl = *reinterpret_cast<const uint4*>(W2l + (size_t)row * HH + c * 8);
        *reinterpret_cast<uint4*>(smem + S_WH + row * PITCH + c * 16) = bh;
        *reinterpret_cast<uint4*>(smem + S_WL + row * PITCH + c * 16) = bl;
    }
    __syncthreads();

    // ================= GEMM 2 =================
    #pragma unroll
    for (int i = 0; i < 8; i++)
        #pragma unroll
        for (int j = 0; j < 4; j++) acc[i][j] = 0.f;

    #pragma unroll
    for (int ks = 0; ks < 8; ks++) {
        uint32_t aH[4], aL[4];
        ldsm4(aH, aHb + ks * 32);
        ldsm4(aL, aLb + ks * 32);
        #pragma unroll
        for (int np = 0; np < 4; np++) {
            uint32_t bh[4], bl[4];
            ldsm4(bh, bHb + np * (16 * PITCH) + ks * 32);
            ldsm4(bl, bLb + np * (16 * PITCH) + ks * 32);
            float* c0 = acc[2 * np];
            float* c1 = acc[2 * np + 1];
            mma16816(c0, aH, bh[0], bh[2]);
            mma16816(c0, aL, bh[0], bh[2]);
            mma16816(c0, aH, bl[0], bl[2]);
            mma16816(c1, aH, bh[1], bh[3]);
            mma16816(c1, aL, bh[1], bh[3]);
            mma16816(c1, aH, bl[1], bl[3]);
        }
    }

    // ---- epilogue 2: + b2, fp32 to global ----
    {
        const int r0 = block_m + wr * 16 + quad;
        const int r1 = r0 + 8;
        #pragma unroll
        for (int np = 0; np < 4; np++) {
            #pragma unroll
            for (int s = 0; s < 2; s++) {
                int nt = 2 * np + s;
                int col = wc * 64 + np * 16 + s * 8 + qc;
                float b0 = __ldg(bias2 + col), b1v = __ldg(bias2 + col + 1);
                if (r0 < M)
                    *reinterpret_cast<float2*>(Out + (size_t)r0 * HH + col) =
                        make_float2(acc[nt][0] + b0, acc[nt][1] + b1v);
                if (r1 < M)
                    *reinterpret_cast<float2*>(Out + (size_t)r1 * HH + col) =
                        make_float2(acc[nt][2] + b0, acc[nt][3] + b1v);
            }
        }
    }
}

// ---------------------------------------------------------------------------
// Pooling (batch sorted): block = 128 nodes, thread = feature column.
// ---------------------------------------------------------------------------
__global__ void pool_kernel(const float* __restrict__ h, const int* __restrict__ batch,
                            float* __restrict__ out, float* __restrict__ cnt) {
    __shared__ int sbv[128];
    const int b0 = blockIdx.x * 128;
    const int c = threadIdx.x;
    const int nrows = min(128, NN - b0);
    if (c < nrows) sbv[c] = batch[b0 + c];
    __syncthreads();

    int cur = sbv[0];
    float acc = 0.f, cn = 0.f;
    for (int i = 0; i < nrows; i++) {
        int g = sbv[i];
        if (g != cur) {
            atomicAdd(&out[cur * 128 + c], acc);
            if (c == 0) atomicAdd(&cnt[cur], cn);
            acc = 0.f; cn = 0.f; cur = g;
        }
        acc += h[(size_t)(b0 + i) * 128 + c];
        cn += 1.f;
    }
    atomicAdd(&out[cur * 128 + c], acc);
    if (c == 0) atomicAdd(&cnt[cur], cn);
}

__global__ void zero_out_kernel(float* __restrict__ out, float* __restrict__ cnt) {
    int i = blockIdx.x * blockDim.x + threadIdx.x;
    if (i < GG * HH) out[i] = 0.f;
    if (i < GG) cnt[i] = 0.f;
}

__global__ void div_kernel(float* __restrict__ out, const float* __restrict__ cnt) {
    int i = blockIdx.x * blockDim.x + threadIdx.x;
    if (i < GG * HH) out[i] /= fmaxf(cnt[i >> 7], 1.f);
}

// ---------------------------------------------------------------------------
// Launch
// ---------------------------------------------------------------------------
extern "C" void kernel_launch(void* const* d_in, const int* in_sizes, int n_in,
                              void* d_out, int out_size) {
    (void)in_sizes; (void)n_in; (void)out_size;

    const float* x          = (const float*)d_in[0];
    const int*   edge_index = (const int*)d_in[1];
    const int*   batch      = (const int*)d_in[2];
    const int*   e_src = edge_index;
    const int*   e_dst = edge_index + EE;
    float* out = (float*)d_out;

    void *ph, *pagg, *pwH, *pwL, *pcnt;
    cudaGetSymbolAddress(&ph,   g_h);
    cudaGetSymbolAddress(&pagg, g_agg);
    cudaGetSymbolAddress(&pwH,  g_wH);
    cudaGetSymbolAddress(&pwL,  g_wL);
    cudaGetSymbolAddress(&pcnt, g_cnt);
    float* h   = (float*)ph;
    float* agg = (float*)pagg;
    __nv_bfloat16* wH = (__nv_bfloat16*)pwH;
    __nv_bfloat16* wL = (__nv_bfloat16*)pwL;
    float* cnt = (float*)pcnt;

    cudaFuncSetAttribute(fused_mlp,
                         cudaFuncAttributeMaxDynamicSharedMemorySize, FUSED_SMEM);

    const int n4 = NN * HH / 4;
    const int zero_blocks    = (n4 + 255) / 256;
    const int scatter_warps  = (EE + 1) / 2;
    const int scatter_blocks = (scatter_warps * 32 + 255) / 256;
    const int fused_blocks   = (NN + 63) / 64;     // 1563
    const int wconv_blocks   = (6 * HH * HH + 255) / 256;

    wconv_kernel<<<wconv_blocks, 256>>>((const float*)d_in[3], (const float*)d_in[5],
                                        (const float*)d_in[7], (const float*)d_in[9],
                                        (const float*)d_in[11], (const float*)d_in[13],
                                        wH, wL);

    const float* in = x;
    for (int l = 0; l < 3; l++) {
        const float* b1 = (const float*)d_in[3 + 4 * l + 1];
        const float* b2 = (const float*)d_in[3 + 4 * l + 3];
        __nv_bfloat16* w1H = wH + (size_t)(2 * l) * HH * HH;
        __nv_bfloat16* w1L = wL + (size_t)(2 * l) * HH * HH;
        __nv_bfloat16* w2H = wH + (size_t)(2 * l + 1) * HH * HH;
        __nv_bfloat16* w2L = wL + (size_t)(2 * l + 1) * HH * HH;

        zero_agg_kernel<<<zero_blocks, 256>>>((float4*)agg, n4);
        scatter_kernel<<<scatter_blocks, 256>>>(in, e_src, e_dst, agg);
        fused_mlp<<<fused_blocks, 256, FUSED_SMEM>>>(
            in, agg, w1H, w1L, w2H, w2L, b1, b2, h, NN);
        in = h;
    }

    zero_out_kernel<<<(GG * HH + 255) / 256, 256>>>(out, cnt);
    pool_kernel<<<(NN + 127) / 128, 128>>>(h, batch, out, cnt);
    div_kernel<<<(GG * HH + 255) / 256, 256>>>(out, cnt);
}

// round 6
// speedup vs baseline: 3.9442x; 1.3691x over previous
#include <cuda_runtime.h>
#include <cuda_bf16.h>
#include <cstdint>
#include <cstddef>

#define NN 100000
#define EE 1600000
#define HH 128
#define GG 128
#define SCAN_BLK 1024
#define SCAN_NB ((NN + SCAN_BLK - 1) / SCAN_BLK)   // 98

// ---------------------------------------------------------------------------
// Scratch (__device__ globals; allocation-free rule)
// ---------------------------------------------------------------------------
__device__ float g_h[(size_t)NN * HH];            // layer output (fp32)
__device__ float g_xagg[(size_t)NN * HH];         // x + sum_neighbors (fp32)
__device__ __nv_bfloat16 g_wH[6 * HH * HH];       // transposed weights hi ([n][k])
__device__ __nv_bfloat16 g_wL[6 * HH * HH];       // transposed weights lo
__device__ float g_cnt[GG];
__device__ int g_deg[NN];
__device__ int g_rowptr[NN];
__device__ int g_head[NN];
__device__ int g_csrc[EE];
__device__ int g_bsum[SCAN_NB];

// ---------------------------------------------------------------------------
// helpers
// ---------------------------------------------------------------------------
__device__ __forceinline__ uint32_t smem_u32(const void* p) {
    uint32_t a;
    asm("{ .reg .u64 t; cvta.to.shared.u64 t, %1; cvt.u32.u64 %0, t; }" : "=r"(a) : "l"(p));
    return a;
}

__device__ __forceinline__ void ldsm4(uint32_t* r, uint32_t addr) {
    asm volatile("ldmatrix.sync.aligned.m8n8.x4.shared.b16 {%0,%1,%2,%3}, [%4];"
                 : "=r"(r[0]), "=r"(r[1]), "=r"(r[2]), "=r"(r[3]) : "r"(addr));
}

__device__ __forceinline__ void mma16816(float* c, const uint32_t* a, uint32_t b0, uint32_t b1) {
    asm volatile("mma.sync.aligned.m16n8k16.row.col.f32.bf16.bf16.f32 "
                 "{%0,%1,%2,%3}, {%4,%5,%6,%7}, {%8,%9}, {%0,%1,%2,%3};"
                 : "+f"(c[0]), "+f"(c[1]), "+f"(c[2]), "+f"(c[3])
                 : "r"(a[0]), "r"(a[1]), "r"(a[2]), "r"(a[3]), "r"(b0), "r"(b1));
}

__device__ __forceinline__ uint32_t pk(__nv_bfloat16 a, __nv_bfloat16 b) {
    __nv_bfloat162 t(a, b);
    return *reinterpret_cast<uint32_t*>(&t);
}

__device__ __forceinline__ uint32_t split_hi(float v0, float v1, uint32_t& lo) {
    __nv_bfloat16 h0 = __float2bfloat16(v0), h1 = __float2bfloat16(v1);
    lo = pk(__float2bfloat16(v0 - __bfloat162float(h0)),
            __float2bfloat16(v1 - __bfloat162float(h1)));
    return pk(h0, h1);
}

// ---------------------------------------------------------------------------
// CSR build (once per launch): edges grouped by destination
// ---------------------------------------------------------------------------
__global__ void zero_deg_kernel(int* __restrict__ deg) {
    int i = blockIdx.x * blockDim.x + threadIdx.x;
    if (i < NN) deg[i] = 0;
}

__global__ void hist_kernel(const int* __restrict__ dst, int* __restrict__ deg) {
    int i = blockIdx.x * blockDim.x + threadIdx.x;
    if (i < EE) atomicAdd(&deg[dst[i]], 1);
}

__global__ void scan1_kernel(const int* __restrict__ deg, int* __restrict__ rowptr,
                             int* __restrict__ bsum) {
    __shared__ int sh[SCAN_BLK];
    int i = blockIdx.x * SCAN_BLK + threadIdx.x;
    int v = (i < NN) ? deg[i] : 0;
    sh[threadIdx.x] = v;
    __syncthreads();
    #pragma unroll
    for (int off = 1; off < SCAN_BLK; off <<= 1) {
        int t = (threadIdx.x >= off) ? sh[threadIdx.x - off] : 0;
        __syncthreads();
        sh[threadIdx.x] += t;
        __syncthreads();
    }
    if (i < NN) rowptr[i] = sh[threadIdx.x] - v;       // exclusive
    if (threadIdx.x == SCAN_BLK - 1) bsum[blockIdx.x] = sh[SCAN_BLK - 1];
}

__global__ void scan2_kernel(int* __restrict__ bsum) {
    if (threadIdx.x == 0) {
        int run = 0;
        for (int i = 0; i < SCAN_NB; i++) { int t = bsum[i]; bsum[i] = run; run += t; }
    }
}

__global__ void scan3_kernel(int* __restrict__ rowptr, int* __restrict__ head,
                             const int* __restrict__ bsum) {
    int i = blockIdx.x * blockDim.x + threadIdx.x;
    if (i < NN) {
        int r = rowptr[i] + bsum[i >> 10];
        rowptr[i] = r;
        head[i] = r;
    }
}

__global__ void fill_kernel(const int* __restrict__ src, const int* __restrict__ dst,
                            int* __restrict__ head, int* __restrict__ csrc) {
    int i = blockIdx.x * blockDim.x + threadIdx.x;
    if (i < EE) {
        int pos = atomicAdd(&head[dst[i]], 1);
        csrc[pos] = src[i];
    }
}

// ---------------------------------------------------------------------------
// gather: warp per node. xagg[i] = in[i] + sum_{j in csr(i)} in[j]
// lane handles one float4 (4 features). 4-neighbor unrolled for MLP.
// ---------------------------------------------------------------------------
__global__ __launch_bounds__(256)
void gather_kernel(const float* __restrict__ In, const int* __restrict__ csrc,
                   const int* __restrict__ rowptr, const int* __restrict__ deg,
                   float* __restrict__ xagg) {
    int node = (blockIdx.x * blockDim.x + threadIdx.x) >> 5;
    int lane = threadIdx.x & 31;
    if (node >= NN) return;
    const float4* base = reinterpret_cast<const float4*>(In);

    float4 a0 = base[(size_t)node * 32 + lane];    // self term
    float4 a1 = make_float4(0.f, 0.f, 0.f, 0.f);
    float4 a2 = a1, a3 = a1;

    int st = rowptr[node];
    int dg = deg[node];
    int j = 0;
    for (; j + 4 <= dg; j += 4) {
        int s0 = __ldg(csrc + st + j);
        int s1 = __ldg(csrc + st + j + 1);
        int s2 = __ldg(csrc + st + j + 2);
        int s3 = __ldg(csrc + st + j + 3);
        float4 v0 = base[(size_t)s0 * 32 + lane];
        float4 v1 = base[(size_t)s1 * 32 + lane];
        float4 v2 = base[(size_t)s2 * 32 + lane];
        float4 v3 = base[(size_t)s3 * 32 + lane];
        a0.x += v0.x; a0.y += v0.y; a0.z += v0.z; a0.w += v0.w;
        a1.x += v1.x; a1.y += v1.y; a1.z += v1.z; a1.w += v1.w;
        a2.x += v2.x; a2.y += v2.y; a2.z += v2.z; a2.w += v2.w;
        a3.x += v3.x; a3.y += v3.y; a3.z += v3.z; a3.w += v3.w;
    }
    for (; j < dg; j++) {
        int s = __ldg(csrc + st + j);
        float4 v = base[(size_t)s * 32 + lane];
        a0.x += v.x; a0.y += v.y; a0.z += v.z; a0.w += v.w;
    }
    a0.x += a1.x + a2.x + a3.x;
    a0.y += a1.y + a2.y + a3.y;
    a0.z += a1.z + a2.z + a3.z;
    a0.w += a1.w + a2.w + a3.w;
    reinterpret_cast<float4*>(xagg)[(size_t)node * 32 + lane] = a0;
}

// ---------------------------------------------------------------------------
// Weights: transpose + split. out[m][n][k] = W_m[k][n]
// ---------------------------------------------------------------------------
__global__ void wconv_kernel(const float* __restrict__ W0, const float* __restrict__ W1,
                             const float* __restrict__ W2, const float* __restrict__ W3,
                             const float* __restrict__ W4, const float* __restrict__ W5,
                             __nv_bfloat16* __restrict__ wh, __nv_bfloat16* __restrict__ wl) {
    int i = blockIdx.x * blockDim.x + threadIdx.x;
    if (i >= 6 * HH * HH) return;
    int m = i / (HH * HH);
    int r = i % (HH * HH);
    int n = r / HH;
    int k = r % HH;
    const float* W = (m == 0) ? W0 : (m == 1) ? W1 : (m == 2) ? W2
                   : (m == 3) ? W3 : (m == 4) ? W4 : W5;
    float v = W[k * HH + n];
    __nv_bfloat16 h = __float2bfloat16(v);
    wh[i] = h;
    wl[i] = __float2bfloat16(v - __bfloat162float(h));
}

// ---------------------------------------------------------------------------
// Fused MLP: out[M,128] = relu(A @ W1 + b1) @ W2 + b2,  A = xagg (fp32)
// Split-precision 3-pass bf16 mma.sync. M-tile 64, 256 threads. 2 CTAs/SM.
// ---------------------------------------------------------------------------
#define PITCH 272
#define S_AH 0
#define S_AL (64 * PITCH)
#define S_WH (2 * 64 * PITCH)
#define S_WL (S_WH + 128 * PITCH)
#define FUSED_SMEM (S_WL + 128 * PITCH)

__global__ __launch_bounds__(256, 2)
void fused_mlp(const float* __restrict__ A,
               const __nv_bfloat16* __restrict__ W1h, const __nv_bfloat16* __restrict__ W1l,
               const __nv_bfloat16* __restrict__ W2h, const __nv_bfloat16* __restrict__ W2l,
               const float* __restrict__ bias1, const float* __restrict__ bias2,
               float* __restrict__ Out, int M) {
    extern __shared__ __align__(16) char smem[];
    const uint32_t sb = smem_u32(smem);
    const int tid = threadIdx.x;
    const int wid = tid >> 5, lane = tid & 31;
    const int block_m = blockIdx.x * 64;

    // ---- stage A (fp32 -> hi/lo bf16) ----
    #pragma unroll
    for (int it = 0; it < 4; it++) {
        int idx = it * 256 + tid;
        int row = idx >> 4;
        int c   = idx & 15;
        int gm  = block_m + row;
        uint4 vh = make_uint4(0, 0, 0, 0), vl = vh;
        if (gm < M) {
            const float* pa = A + (size_t)gm * HH + c * 8;
            float4 a0 = *reinterpret_cast<const float4*>(pa);
            float4 a1 = *reinterpret_cast<const float4*>(pa + 4);
            float fv[8] = {a0.x, a0.y, a0.z, a0.w, a1.x, a1.y, a1.z, a1.w};
            uint32_t hp_[4], lp_[4];
            #pragma unroll
            for (int j = 0; j < 4; j++) hp_[j] = split_hi(fv[2 * j], fv[2 * j + 1], lp_[j]);
            vh = make_uint4(hp_[0], hp_[1], hp_[2], hp_[3]);
            vl = make_uint4(lp_[0], lp_[1], lp_[2], lp_[3]);
        }
        *reinterpret_cast<uint4*>(smem + S_AH + row * PITCH + c * 16) = vh;
        *reinterpret_cast<uint4*>(smem + S_AL + row * PITCH + c * 16) = vl;
    }
    // ---- stage W1 ----
    #pragma unroll
    for (int it = 0; it < 8; it++) {
        int idx = it * 256 + tid;
        int row = idx >> 4;
        int c   = idx & 15;
        uint4 bh = *reinterpret_cast<const uint4*>(W1h + (size_t)row * HH + c * 8);
        uint4 bl = *reinterpret_cast<const uint4*>(W1l + (size_t)row * HH + c * 8);
        *reinterpret_cast<uint4*>(smem + S_WH + row * PITCH + c * 16) = bh;
        *reinterpret_cast<uint4*>(smem + S_WL + row * PITCH + c * 16) = bl;
    }
    __syncthreads();

    const int wr = wid >> 1;
    const int wc = wid & 1;
    const int arow = lane & 15;
    const int akc  = (lane & 16) >> 1;
    const uint32_t aHb = sb + S_AH + (wr * 16 + arow) * PITCH + akc * 2;
    const uint32_t aLb = aHb + (S_AL - S_AH);
    const uint32_t bHb = sb + S_WH + (wc * 64 + arow) * PITCH + akc * 2;
    const uint32_t bLb = bHb + (S_WL - S_WH);
    const int quad = lane >> 2;
    const int qc   = (lane & 3) * 2;

    float acc[8][4];

    // ================= GEMM 1 =================
    #pragma unroll
    for (int i = 0; i < 8; i++)
        #pragma unroll
        for (int j = 0; j < 4; j++) acc[i][j] = 0.f;

    #pragma unroll
    for (int ks = 0; ks < 8; ks++) {
        uint32_t aH[4], aL[4];
        ldsm4(aH, aHb + ks * 32);
        ldsm4(aL, aLb + ks * 32);
        #pragma unroll
        for (int np = 0; np < 4; np++) {
            uint32_t bh[4], bl[4];
            ldsm4(bh, bHb + np * (16 * PITCH) + ks * 32);
            ldsm4(bl, bLb + np * (16 * PITCH) + ks * 32);
            float* c0 = acc[2 * np];
            float* c1 = acc[2 * np + 1];
            mma16816(c0, aH, bh[0], bh[2]);
            mma16816(c0, aL, bh[0], bh[2]);
            mma16816(c0, aH, bl[0], bl[2]);
            mma16816(c1, aH, bh[1], bh[3]);
            mma16816(c1, aL, bh[1], bh[3]);
            mma16816(c1, aH, bl[1], bl[3]);
        }
    }
    __syncthreads();

    // ---- epilogue 1: relu(acc + b1) -> hi/lo -> A smem ----
    {
        const int lr0 = wr * 16 + quad;
        #pragma unroll
        for (int np = 0; np < 4; np++) {
            #pragma unroll
            for (int s = 0; s < 2; s++) {
                int nt = 2 * np + s;
                int col = wc * 64 + np * 16 + s * 8 + qc;
                float b0 = __ldg(bias1 + col), b1v = __ldg(bias1 + col + 1);
                float v00 = fmaxf(acc[nt][0] + b0, 0.f);
                float v01 = fmaxf(acc[nt][1] + b1v, 0.f);
                float v10 = fmaxf(acc[nt][2] + b0, 0.f);
                float v11 = fmaxf(acc[nt][3] + b1v, 0.f);
                uint32_t lo0, lo1;
                uint32_t hi0 = split_hi(v00, v01, lo0);
                uint32_t hi1 = split_hi(v10, v11, lo1);
                *reinterpret_cast<uint32_t*>(smem + S_AH + lr0 * PITCH + col * 2) = hi0;
                *reinterpret_cast<uint32_t*>(smem + S_AL + lr0 * PITCH + col * 2) = lo0;
                *reinterpret_cast<uint32_t*>(smem + S_AH + (lr0 + 8) * PITCH + col * 2) = hi1;
                *reinterpret_cast<uint32_t*>(smem + S_AL + (lr0 + 8) * PITCH + col * 2) = lo1;
            }
        }
    }
    // ---- stage W2 ----
    #pragma unroll
    for (int it = 0; it < 8; it++) {
        int idx = it * 256 + tid;
        int row = idx >> 4;
        int c   = idx & 15;
        uint4 bh = *reinterpret_cast<const uint4*>(W2h + (size_t)row * HH + c * 8);
        uint4 bl = *reinterpret_cast<const uint4*>(W2l + (size_t)row * HH + c * 8);
        *reinterpret_cast<uint4*>(smem + S_WH + row * PITCH + c * 16) = bh;
        *reinterpret_cast<uint4*>(smem + S_WL + row * PITCH + c * 16) = bl;
    }
    __syncthreads();

    // ================= GEMM 2 =================
    #pragma unroll
    for (int i = 0; i < 8; i++)
        #pragma unroll
        for (int j = 0; j < 4; j++) acc[i][j] = 0.f;

    #pragma unroll
    for (int ks = 0; ks < 8; ks++) {
        uint32_t aH[4], aL[4];
        ldsm4(aH, aHb + ks * 32);
        ldsm4(aL, aLb + ks * 32);
        #pragma unroll
        for (int np = 0; np < 4; np++) {
            uint32_t bh[4], bl[4];
            ldsm4(bh, bHb + np * (16 * PITCH) + ks * 32);
            ldsm4(bl, bLb + np * (16 * PITCH) + ks * 32);
            float* c0 = acc[2 * np];
            float* c1 = acc[2 * np + 1];
            mma16816(c0, aH, bh[0], bh[2]);
            mma16816(c0, aL, bh[0], bh[2]);
            mma16816(c0, aH, bl[0], bl[2]);
            mma16816(c1, aH, bh[1], bh[3]);
            mma16816(c1, aL, bh[1], bh[3]);
            mma16816(c1, aH, bl[1], bl[3]);
        }
    }

    // ---- epilogue 2 ----
    {
        const int r0 = block_m + wr * 16 + quad;
        const int r1 = r0 + 8;
        #pragma unroll
        for (int np = 0; np < 4; np++) {
            #pragma unroll
            for (int s = 0; s < 2; s++) {
                int nt = 2 * np + s;
                int col = wc * 64 + np * 16 + s * 8 + qc;
                float b0 = __ldg(bias2 + col), b1v = __ldg(bias2 + col + 1);
                if (r0 < M)
                    *reinterpret_cast<float2*>(Out + (size_t)r0 * HH + col) =
                        make_float2(acc[nt][0] + b0, acc[nt][1] + b1v);
                if (r1 < M)
                    *reinterpret_cast<float2*>(Out + (size_t)r1 * HH + col) =
                        make_float2(acc[nt][2] + b0, acc[nt][3] + b1v);
            }
        }
    }
}

// ---------------------------------------------------------------------------
// Pooling (batch sorted)
// ---------------------------------------------------------------------------
__global__ void pool_kernel(const float* __restrict__ h, const int* __restrict__ batch,
                            float* __restrict__ out, float* __restrict__ cnt) {
    __shared__ int sbv[128];
    const int b0 = blockIdx.x * 128;
    const int c = threadIdx.x;
    const int nrows = min(128, NN - b0);
    if (c < nrows) sbv[c] = batch[b0 + c];
    __syncthreads();

    int cur = sbv[0];
    float acc = 0.f, cn = 0.f;
    for (int i = 0; i < nrows; i++) {
        int g = sbv[i];
        if (g != cur) {
            atomicAdd(&out[cur * 128 + c], acc);
            if (c == 0) atomicAdd(&cnt[cur], cn);
            acc = 0.f; cn = 0.f; cur = g;
        }
        acc += h[(size_t)(b0 + i) * 128 + c];
        cn += 1.f;
    }
    atomicAdd(&out[cur * 128 + c], acc);
    if (c == 0) atomicAdd(&cnt[cur], cn);
}

__global__ void zero_out_kernel(float* __restrict__ out, float* __restrict__ cnt) {
    int i = blockIdx.x * blockDim.x + threadIdx.x;
    if (i < GG * HH) out[i] = 0.f;
    if (i < GG) cnt[i] = 0.f;
}

__global__ void div_kernel(float* __restrict__ out, const float* __restrict__ cnt) {
    int i = blockIdx.x * blockDim.x + threadIdx.x;
    if (i < GG * HH) out[i] /= fmaxf(cnt[i >> 7], 1.f);
}

// ---------------------------------------------------------------------------
// Launch
// ---------------------------------------------------------------------------
extern "C" void kernel_launch(void* const* d_in, const int* in_sizes, int n_in,
                              void* d_out, int out_size) {
    (void)in_sizes; (void)n_in; (void)out_size;

    const float* x          = (const float*)d_in[0];
    const int*   edge_index = (const int*)d_in[1];
    const int*   batch      = (const int*)d_in[2];
    const int*   e_src = edge_index;
    const int*   e_dst = edge_index + EE;
    float* out = (float*)d_out;

    void *ph, *pxa, *pwH, *pwL, *pcnt, *pdeg, *prp, *phd, *pcs, *pbs;
    cudaGetSymbolAddress(&ph,  g_h);
    cudaGetSymbolAddress(&pxa, g_xagg);
    cudaGetSymbolAddress(&pwH, g_wH);
    cudaGetSymbolAddress(&pwL, g_wL);
    cudaGetSymbolAddress(&pcnt, g_cnt);
    cudaGetSymbolAddress(&pdeg, g_deg);
    cudaGetSymbolAddress(&prp,  g_rowptr);
    cudaGetSymbolAddress(&phd,  g_head);
    cudaGetSymbolAddress(&pcs,  g_csrc);
    cudaGetSymbolAddress(&pbs,  g_bsum);
    float* h    = (float*)ph;
    float* xagg = (float*)pxa;
    __nv_bfloat16* wH = (__nv_bfloat16*)pwH;
    __nv_bfloat16* wL = (__nv_bfloat16*)pwL;
    float* cnt = (float*)pcnt;
    int* deg    = (int*)pdeg;
    int* rowptr = (int*)prp;
    int* head   = (int*)phd;
    int* csrc   = (int*)pcs;
    int* bsum   = (int*)pbs;

    cudaFuncSetAttribute(fused_mlp,
                         cudaFuncAttributeMaxDynamicSharedMemorySize, FUSED_SMEM);

    const int nn_blocks     = (NN + 255) / 256;
    const int ee_blocks     = (EE + 255) / 256;
    const int gather_blocks = (NN * 32 + 255) / 256;  // warp per node
    const int fused_blocks  = (NN + 63) / 64;
    const int wconv_blocks  = (6 * HH * HH + 255) / 256;

    // ---- CSR build (once) ----
    zero_deg_kernel<<<nn_blocks, 256>>>(deg);
    hist_kernel<<<ee_blocks, 256>>>(e_dst, deg);
    scan1_kernel<<<SCAN_NB, SCAN_BLK>>>(deg, rowptr, bsum);
    scan2_kernel<<<1, 32>>>(bsum);
    scan3_kernel<<<nn_blocks, 256>>>(rowptr, head, bsum);
    fill_kernel<<<ee_blocks, 256>>>(e_src, e_dst, head, csrc);

    wconv_kernel<<<wconv_blocks, 256>>>((const float*)d_in[3], (const float*)d_in[5],
                                        (const float*)d_in[7], (const float*)d_in[9],
                                        (const float*)d_in[11], (const float*)d_in[13],
                                        wH, wL);

    const float* in = x;
    for (int l = 0; l < 3; l++) {
        const float* b1 = (const float*)d_in[3 + 4 * l + 1];
        const float* b2 = (const float*)d_in[3 + 4 * l + 3];
        __nv_bfloat16* w1H = wH + (size_t)(2 * l) * HH * HH;
        __nv_bfloat16* w1L = wL + (size_t)(2 * l) * HH * HH;
        __nv_bfloat16* w2H = wH + (size_t)(2 * l + 1) * HH * HH;
        __nv_bfloat16* w2L = wL + (size_t)(2 * l + 1) * HH * HH;

        gather_kernel<<<gather_blocks, 256>>>(in, csrc, rowptr, deg, xagg);
        fused_mlp<<<fused_blocks, 256, FUSED_SMEM>>>(
            xagg, w1H, w1L, w2H, w2L, b1, b2, h, NN);
        in = h;
    }

    zero_out_kernel<<<(GG * HH + 255) / 256, 256>>>(out, cnt);
    pool_kernel<<<(NN + 127) / 128, 128>>>(h, batch, out, cnt);
    div_kernel<<<(GG * HH + 255) / 256, 256>>>(out, cnt);
}

// round 7
// speedup vs baseline: 4.5267x; 1.1477x over previous
#include <cuda_runtime.h>
#include <cuda_bf16.h>
#include <cstdint>
#include <cstddef>

#define NN 100000
#define EE 1600000
#define HH 128
#define GG 128
#define SCAN_BLK 1024
#define SCAN_NB ((NN + SCAN_BLK - 1) / SCAN_BLK)   // 98

// ---------------------------------------------------------------------------
// Scratch (__device__ globals; allocation-free rule)
// ---------------------------------------------------------------------------
__device__ float g_h[(size_t)NN * HH];              // layer output (fp32)
__device__ __nv_bfloat16 g_aH[(size_t)NN * HH];     // xagg hi split
__device__ __nv_bfloat16 g_aL[(size_t)NN * HH];     // xagg lo split
__device__ __nv_bfloat16 g_wH[6 * HH * HH];         // transposed weights hi ([n][k])
__device__ __nv_bfloat16 g_wL[6 * HH * HH];         // transposed weights lo
__device__ float g_cnt[GG];
__device__ int g_deg[NN];
__device__ int g_rowptr[NN];
__device__ int g_head[NN];
__device__ int g_csrc[EE];
__device__ int g_bsum[SCAN_NB];

// ---------------------------------------------------------------------------
// helpers
// ---------------------------------------------------------------------------
__device__ __forceinline__ uint32_t smem_u32(const void* p) {
    uint32_t a;
    asm("{ .reg .u64 t; cvta.to.shared.u64 t, %1; cvt.u32.u64 %0, t; }" : "=r"(a) : "l"(p));
    return a;
}

__device__ __forceinline__ void ldsm4(uint32_t* r, uint32_t addr) {
    asm volatile("ldmatrix.sync.aligned.m8n8.x4.shared.b16 {%0,%1,%2,%3}, [%4];"
                 : "=r"(r[0]), "=r"(r[1]), "=r"(r[2]), "=r"(r[3]) : "r"(addr));
}

__device__ __forceinline__ void mma16816(float* c, const uint32_t* a, uint32_t b0, uint32_t b1) {
    asm volatile("mma.sync.aligned.m16n8k16.row.col.f32.bf16.bf16.f32 "
                 "{%0,%1,%2,%3}, {%4,%5,%6,%7}, {%8,%9}, {%0,%1,%2,%3};"
                 : "+f"(c[0]), "+f"(c[1]), "+f"(c[2]), "+f"(c[3])
                 : "r"(a[0]), "r"(a[1]), "r"(a[2]), "r"(a[3]), "r"(b0), "r"(b1));
}

__device__ __forceinline__ uint32_t pk(__nv_bfloat16 a, __nv_bfloat16 b) {
    __nv_bfloat162 t(a, b);
    return *reinterpret_cast<uint32_t*>(&t);
}

__device__ __forceinline__ uint32_t split_hi(float v0, float v1, uint32_t& lo) {
    __nv_bfloat16 h0 = __float2bfloat16(v0), h1 = __float2bfloat16(v1);
    lo = pk(__float2bfloat16(v0 - __bfloat162float(h0)),
            __float2bfloat16(v1 - __bfloat162float(h1)));
    return pk(h0, h1);
}

__device__ __forceinline__ void cp16(uint32_t dst, const void* src, int sz) {
    asm volatile("cp.async.cg.shared.global [%0], [%1], 16, %2;"
                 :: "r"(dst), "l"(src), "r"(sz) : "memory");
}
#define CP_COMMIT() asm volatile("cp.async.commit_group;" ::: "memory")
#define CP_WAIT0()  asm volatile("cp.async.wait_group 0;" ::: "memory")

// ---------------------------------------------------------------------------
// CSR build (once per launch): edges grouped by destination
// ---------------------------------------------------------------------------
__global__ void zero_deg_kernel(int* __restrict__ deg) {
    int i = blockIdx.x * blockDim.x + threadIdx.x;
    if (i < NN) deg[i] = 0;
}

__global__ void hist_kernel(const int* __restrict__ dst, int* __restrict__ deg) {
    int i = blockIdx.x * blockDim.x + threadIdx.x;
    if (i < EE) atomicAdd(&deg[dst[i]], 1);
}

__global__ void scan1_kernel(const int* __restrict__ deg, int* __restrict__ rowptr,
                             int* __restrict__ bsum) {
    __shared__ int sh[SCAN_BLK];
    int i = blockIdx.x * SCAN_BLK + threadIdx.x;
    int v = (i < NN) ? deg[i] : 0;
    sh[threadIdx.x] = v;
    __syncthreads();
    #pragma unroll
    for (int off = 1; off < SCAN_BLK; off <<= 1) {
        int t = (threadIdx.x >= off) ? sh[threadIdx.x - off] : 0;
        __syncthreads();
        sh[threadIdx.x] += t;
        __syncthreads();
    }
    if (i < NN) rowptr[i] = sh[threadIdx.x] - v;       // exclusive
    if (threadIdx.x == SCAN_BLK - 1) bsum[blockIdx.x] = sh[SCAN_BLK - 1];
}

__global__ void scan2_kernel(int* __restrict__ bsum) {
    __shared__ int sh[128];
    int i = threadIdx.x;
    int v = (i < SCAN_NB) ? bsum[i] : 0;
    sh[i] = v;
    __syncthreads();
    #pragma unroll
    for (int off = 1; off < 128; off <<= 1) {
        int t = (i >= off) ? sh[i - off] : 0;
        __syncthreads();
        sh[i] += t;
        __syncthreads();
    }
    if (i < SCAN_NB) bsum[i] = sh[i] - v;              // exclusive
}

__global__ void scan3_kernel(int* __restrict__ rowptr, int* __restrict__ head,
                             const int* __restrict__ bsum) {
    int i = blockIdx.x * blockDim.x + threadIdx.x;
    if (i < NN) {
        int r = rowptr[i] + bsum[i >> 10];
        rowptr[i] = r;
        head[i] = r;
    }
}

__global__ void fill_kernel(const int* __restrict__ src, const int* __restrict__ dst,
                            int* __restrict__ head, int* __restrict__ csrc) {
    int i = blockIdx.x * blockDim.x + threadIdx.x;
    if (i < EE) {
        int pos = atomicAdd(&head[dst[i]], 1);
        csrc[pos] = src[i];
    }
}

// ---------------------------------------------------------------------------
// gather: warp per node. xagg[i] = in[i] + sum_{j in csr(i)} in[j]
// Output written as bf16 hi/lo split (MLP A-operand ready).
// ---------------------------------------------------------------------------
__global__ __launch_bounds__(256)
void gather_kernel(const float* __restrict__ In, const int* __restrict__ csrc,
                   const int* __restrict__ rowptr, const int* __restrict__ deg,
                   __nv_bfloat16* __restrict__ outH, __nv_bfloat16* __restrict__ outL) {
    int node = (blockIdx.x * blockDim.x + threadIdx.x) >> 5;
    int lane = threadIdx.x & 31;
    if (node >= NN) return;
    const float4* base = reinterpret_cast<const float4*>(In);

    float4 a0 = base[(size_t)node * 32 + lane];    // self term
    float4 a1 = make_float4(0.f, 0.f, 0.f, 0.f);
    float4 a2 = a1, a3 = a1;

    int st = rowptr[node];
    int dg = deg[node];
    int j = 0;
    for (; j + 4 <= dg; j += 4) {
        int s0 = __ldg(csrc + st + j);
        int s1 = __ldg(csrc + st + j + 1);
        int s2 = __ldg(csrc + st + j + 2);
        int s3 = __ldg(csrc + st + j + 3);
        float4 v0 = base[(size_t)s0 * 32 + lane];
        float4 v1 = base[(size_t)s1 * 32 + lane];
        float4 v2 = base[(size_t)s2 * 32 + lane];
        float4 v3 = base[(size_t)s3 * 32 + lane];
        a0.x += v0.x; a0.y += v0.y; a0.z += v0.z; a0.w += v0.w;
        a1.x += v1.x; a1.y += v1.y; a1.z += v1.z; a1.w += v1.w;
        a2.x += v2.x; a2.y += v2.y; a2.z += v2.z; a2.w += v2.w;
        a3.x += v3.x; a3.y += v3.y; a3.z += v3.z; a3.w += v3.w;
    }
    for (; j < dg; j++) {
        int s = __ldg(csrc + st + j);
        float4 v = base[(size_t)s * 32 + lane];
        a0.x += v.x; a0.y += v.y; a0.z += v.z; a0.w += v.w;
    }
    a0.x += a1.x + a2.x + a3.x;
    a0.y += a1.y + a2.y + a3.y;
    a0.z += a1.z + a2.z + a3.z;
    a0.w += a1.w + a2.w + a3.w;

    uint32_t lo0, lo1;
    uint32_t hi0 = split_hi(a0.x, a0.y, lo0);
    uint32_t hi1 = split_hi(a0.z, a0.w, lo1);
    *reinterpret_cast<uint2*>(outH + (size_t)node * HH + lane * 4) = make_uint2(hi0, hi1);
    *reinterpret_cast<uint2*>(outL + (size_t)node * HH + lane * 4) = make_uint2(lo0, lo1);
}

// ---------------------------------------------------------------------------
// Weights: transpose + split. out[m][n][k] = W_m[k][n]
// ---------------------------------------------------------------------------
__global__ void wconv_kernel(const float* __restrict__ W0, const float* __restrict__ W1,
                             const float* __restrict__ W2, const float* __restrict__ W3,
                             const float* __restrict__ W4, const float* __restrict__ W5,
                             __nv_bfloat16* __restrict__ wh, __nv_bfloat16* __restrict__ wl) {
    int i = blockIdx.x * blockDim.x + threadIdx.x;
    if (i >= 6 * HH * HH) return;
    int m = i / (HH * HH);
    int r = i % (HH * HH);
    int n = r / HH;
    int k = r % HH;
    const float* W = (m == 0) ? W0 : (m == 1) ? W1 : (m == 2) ? W2
                   : (m == 3) ? W3 : (m == 4) ? W4 : W5;
    float v = W[k * HH + n];
    __nv_bfloat16 h = __float2bfloat16(v);
    wh[i] = h;
    wl[i] = __float2bfloat16(v - __bfloat162float(h));
}

// ---------------------------------------------------------------------------
// Persistent fused MLP: out[M,128] = relu(A @ W1 + b1) @ W2 + b2
// A arrives pre-split (aH, aL). W1+W2 resident in smem; grid-stride over
// 64-row M-tiles with cp.async double-buffered A prefetch. 512 threads.
// Smem: 2 A-buffers (2x34816) + W1 (69632) + W2 (69632) = 208896 B.
// ---------------------------------------------------------------------------
#define PITCH 272
#define ABUF_SZ 34816                 // hi (17408) + lo (17408)
#define S_W1H 69632
#define S_W1L 104448
#define S_W2H 139264
#define S_W2L 174080
#define FUSED_SMEM 208896
#define MTILE 64
#define NTILES ((NN + MTILE - 1) / MTILE)   // 1563

__device__ __forceinline__ void run_gemm(uint32_t aHb, uint32_t aLb,
                                         uint32_t bHb, uint32_t bLb,
                                         float (&acc)[4][4]) {
    #pragma unroll
    for (int i = 0; i < 4; i++)
        #pragma unroll
        for (int j = 0; j < 4; j++) acc[i][j] = 0.f;
    #pragma unroll
    for (int ks = 0; ks < 8; ks++) {
        uint32_t aH[4], aL[4];
        ldsm4(aH, aHb + ks * 32);
        ldsm4(aL, aLb + ks * 32);
        #pragma unroll
        for (int np = 0; np < 2; np++) {
            uint32_t bh[4], bl[4];
            ldsm4(bh, bHb + np * (16 * PITCH) + ks * 32);
            ldsm4(bl, bLb + np * (16 * PITCH) + ks * 32);
            float* c0 = acc[2 * np];
            float* c1 = acc[2 * np + 1];
            mma16816(c0, aH, bh[0], bh[2]);
            mma16816(c0, aL, bh[0], bh[2]);
            mma16816(c0, aH, bl[0], bl[2]);
            mma16816(c1, aH, bh[1], bh[3]);
            mma16816(c1, aL, bh[1], bh[3]);
            mma16816(c1, aH, bl[1], bl[3]);
        }
    }
}

__device__ __forceinline__ void prefetch_A(uint32_t sb, int buf, int tile,
                                           const __nv_bfloat16* __restrict__ AH,
                                           const __nv_bfloat16* __restrict__ AL,
                                           int M, int tid) {
    uint32_t abase = sb + buf * ABUF_SZ;
    #pragma unroll
    for (int it = 0; it < 2; it++) {
        int idx = it * 512 + tid;       // 0..1023
        int row = idx >> 4, c = idx & 15;
        int gm = tile * MTILE + row;
        int ok = (gm < M) ? 16 : 0;
        int gs = min(gm, M - 1);
        uint32_t d = abase + row * PITCH + c * 16;
        cp16(d,         AH + (size_t)gs * HH + c * 8, ok);
        cp16(d + 17408, AL + (size_t)gs * HH + c * 8, ok);
    }
}

__global__ __launch_bounds__(512, 1)
void fused_mlp_persist(const __nv_bfloat16* __restrict__ AH,
                       const __nv_bfloat16* __restrict__ AL,
                       const __nv_bfloat16* __restrict__ W1h, const __nv_bfloat16* __restrict__ W1l,
                       const __nv_bfloat16* __restrict__ W2h, const __nv_bfloat16* __restrict__ W2l,
                       const float* __restrict__ bias1, const float* __restrict__ bias2,
                       float* __restrict__ Out, int M) {
    extern __shared__ __align__(16) char smem[];
    const uint32_t sb = smem_u32(smem);
    const int tid = threadIdx.x;
    const int wid = tid >> 5, lane = tid & 31;

    // ---- stage all weights once ----
    #pragma unroll
    for (int it = 0; it < 4; it++) {
        int idx = it * 512 + tid;       // 0..2047
        int row = idx >> 4, c = idx & 15;
        size_t go = (size_t)row * HH + c * 8;
        *reinterpret_cast<uint4*>(smem + S_W1H + row * PITCH + c * 16) =
            *reinterpret_cast<const uint4*>(W1h + go);
        *reinterpret_cast<uint4*>(smem + S_W1L + row * PITCH + c * 16) =
            *reinterpret_cast<const uint4*>(W1l + go);
        *reinterpret_cast<uint4*>(smem + S_W2H + row * PITCH + c * 16) =
            *reinterpret_cast<const uint4*>(W2h + go);
        *reinterpret_cast<uint4*>(smem + S_W2L + row * PITCH + c * 16) =
            *reinterpret_cast<const uint4*>(W2l + go);
    }

    int t = blockIdx.x;
    int buf = 0;
    if (t < NTILES) prefetch_A(sb, buf, t, AH, AL, M, tid);
    CP_COMMIT();
    __syncthreads();

    const int wr = wid >> 2;            // 0..3 (16 rows each)
    const int wc = wid & 3;             // 0..3 (32 cols each)
    const int arow = lane & 15;
    const int akc  = (lane & 16) >> 1;  // 0 or 8
    const int quad = lane >> 2;
    const int qc   = (lane & 3) * 2;

    while (t < NTILES) {
        int tn = t + gridDim.x;
        CP_WAIT0();
        __syncthreads();                                  // B1: A(t) ready

        const uint32_t abase = sb + buf * ABUF_SZ;
        const uint32_t aHb = abase + (wr * 16 + arow) * PITCH + akc * 2;
        const uint32_t aLb = aHb + 17408;
        float acc[4][4];

        // ---- GEMM1 ----
        run_gemm(aHb, aLb,
                 sb + S_W1H + (wc * 32 + arow) * PITCH + akc * 2,
                 sb + S_W1L + (wc * 32 + arow) * PITCH + akc * 2, acc);
        __syncthreads();                                  // B2: A reads done

        // ---- epilogue 1: relu(acc+b1) -> hi/lo -> A buffer (mid) ----
        {
            const int lr0 = wr * 16 + quad;
            #pragma unroll
            for (int np = 0; np < 2; np++) {
                #pragma unroll
                for (int s = 0; s < 2; s++) {
                    int nt = 2 * np + s;
                    int col = wc * 32 + np * 16 + s * 8 + qc;
                    float b0 = __ldg(bias1 + col), b1v = __ldg(bias1 + col + 1);
                    float v00 = fmaxf(acc[nt][0] + b0, 0.f);
                    float v01 = fmaxf(acc[nt][1] + b1v, 0.f);
                    float v10 = fmaxf(acc[nt][2] + b0, 0.f);
                    float v11 = fmaxf(acc[nt][3] + b1v, 0.f);
                    uint32_t lo0, lo1;
                    uint32_t hi0 = split_hi(v00, v01, lo0);
                    uint32_t hi1 = split_hi(v10, v11, lo1);
                    char* ab = smem + buf * ABUF_SZ;
                    *reinterpret_cast<uint32_t*>(ab + lr0 * PITCH + col * 2) = hi0;
                    *reinterpret_cast<uint32_t*>(ab + 17408 + lr0 * PITCH + col * 2) = lo0;
                    *reinterpret_cast<uint32_t*>(ab + (lr0 + 8) * PITCH + col * 2) = hi1;
                    *reinterpret_cast<uint32_t*>(ab + 17408 + (lr0 + 8) * PITCH + col * 2) = lo1;
                }
            }
        }
        // prefetch next tile into other buffer (overlaps GEMM2)
        if (tn < NTILES) prefetch_A(sb, buf ^ 1, tn, AH, AL, M, tid);
        CP_COMMIT();
        __syncthreads();                                  // B3: mid visible

        // ---- GEMM2 ----
        run_gemm(aHb, aLb,
                 sb + S_W2H + (wc * 32 + arow) * PITCH + akc * 2,
                 sb + S_W2L + (wc * 32 + arow) * PITCH + akc * 2, acc);

        // ---- epilogue 2: + b2 -> fp32 gmem ----
        {
            const int r0 = t * MTILE + wr * 16 + quad;
            const int r1 = r0 + 8;
            #pragma unroll
            for (int np = 0; np < 2; np++) {
                #pragma unroll
                for (int s = 0; s < 2; s++) {
                    int nt = 2 * np + s;
                    int col = wc * 32 + np * 16 + s * 8 + qc;
                    float b0 = __ldg(bias2 + col), b1v = __ldg(bias2 + col + 1);
                    if (r0 < M)
                        *reinterpret_cast<float2*>(Out + (size_t)r0 * HH + col) =
                            make_float2(acc[nt][0] + b0, acc[nt][1] + b1v);
                    if (r1 < M)
                        *reinterpret_cast<float2*>(Out + (size_t)r1 * HH + col) =
                            make_float2(acc[nt][2] + b0, acc[nt][3] + b1v);
                }
            }
        }
        t = tn;
        buf ^= 1;
    }
}

// ---------------------------------------------------------------------------
// Pooling (batch sorted)
// ---------------------------------------------------------------------------
__global__ void pool_kernel(const float* __restrict__ h, const int* __restrict__ batch,
                            float* __restrict__ out, float* __restrict__ cnt) {
    __shared__ int sbv[128];
    const int b0 = blockIdx.x * 128;
    const int c = threadIdx.x;
    const int nrows = min(128, NN - b0);
    if (c < nrows) sbv[c] = batch[b0 + c];
    __syncthreads();

    int cur = sbv[0];
    float acc = 0.f, cn = 0.f;
    for (int i = 0; i < nrows; i++) {
        int g = sbv[i];
        if (g != cur) {
            atomicAdd(&out[cur * 128 + c], acc);
            if (c == 0) atomicAdd(&cnt[cur], cn);
            acc = 0.f; cn = 0.f; cur = g;
        }
        acc += h[(size_t)(b0 + i) * 128 + c];
        cn += 1.f;
    }
    atomicAdd(&out[cur * 128 + c], acc);
    if (c == 0) atomicAdd(&cnt[cur], cn);
}

__global__ void zero_out_kernel(float* __restrict__ out, float* __restrict__ cnt) {
    int i = blockIdx.x * blockDim.x + threadIdx.x;
    if (i < GG * HH) out[i] = 0.f;
    if (i < GG) cnt[i] = 0.f;
}

__global__ void div_kernel(float* __restrict__ out, const float* __restrict__ cnt) {
    int i = blockIdx.x * blockDim.x + threadIdx.x;
    if (i < GG * HH) out[i] /= fmaxf(cnt[i >> 7], 1.f);
}

// ---------------------------------------------------------------------------
// Launch
// ---------------------------------------------------------------------------
extern "C" void kernel_launch(void* const* d_in, const int* in_sizes, int n_in,
                              void* d_out, int out_size) {
    (void)in_sizes; (void)n_in; (void)out_size;

    const float* x          = (const float*)d_in[0];
    const int*   edge_index = (const int*)d_in[1];
    const int*   batch      = (const int*)d_in[2];
    const int*   e_src = edge_index;
    const int*   e_dst = edge_index + EE;
    float* out = (float*)d_out;

    void *ph, *paH, *paL, *pwH, *pwL, *pcnt, *pdeg, *prp, *phd, *pcs, *pbs;
    cudaGetSymbolAddress(&ph,  g_h);
    cudaGetSymbolAddress(&paH, g_aH);
    cudaGetSymbolAddress(&paL, g_aL);
    cudaGetSymbolAddress(&pwH, g_wH);
    cudaGetSymbolAddress(&pwL, g_wL);
    cudaGetSymbolAddress(&pcnt, g_cnt);
    cudaGetSymbolAddress(&pdeg, g_deg);
    cudaGetSymbolAddress(&prp,  g_rowptr);
    cudaGetSymbolAddress(&phd,  g_head);
    cudaGetSymbolAddress(&pcs,  g_csrc);
    cudaGetSymbolAddress(&pbs,  g_bsum);
    float* h  = (float*)ph;
    __nv_bfloat16* aH = (__nv_bfloat16*)paH;
    __nv_bfloat16* aL = (__nv_bfloat16*)paL;
    __nv_bfloat16* wH = (__nv_bfloat16*)pwH;
    __nv_bfloat16* wL = (__nv_bfloat16*)pwL;
    float* cnt = (float*)pcnt;
    int* deg    = (int*)pdeg;
    int* rowptr = (int*)prp;
    int* head   = (int*)phd;
    int* csrc   = (int*)pcs;
    int* bsum   = (int*)pbs;

    cudaFuncSetAttribute(fused_mlp_persist,
                         cudaFuncAttributeMaxDynamicSharedMemorySize, FUSED_SMEM);

    const int nn_blocks     = (NN + 255) / 256;
    const int ee_blocks     = (EE + 255) / 256;
    const int gather_blocks = (NN * 32 + 255) / 256;  // warp per node
    const int wconv_blocks  = (6 * HH * HH + 255) / 256;

    // ---- CSR build (once) ----
    zero_deg_kernel<<<nn_blocks, 256>>>(deg);
    hist_kernel<<<ee_blocks, 256>>>(e_dst, deg);
    scan1_kernel<<<SCAN_NB, SCAN_BLK>>>(deg, rowptr, bsum);
    scan2_kernel<<<1, 128>>>(bsum);
    scan3_kernel<<<nn_blocks, 256>>>(rowptr, head, bsum);
    fill_kernel<<<ee_blocks, 256>>>(e_src, e_dst, head, csrc);

    wconv_kernel<<<wconv_blocks, 256>>>((const float*)d_in[3], (const float*)d_in[5],
                                        (const float*)d_in[7], (const float*)d_in[9],
                                        (const float*)d_in[11], (const float*)d_in[13],
                                        wH, wL);

    const float* in = x;
    for (int l = 0; l < 3; l++) {
        const float* b1 = (const float*)d_in[3 + 4 * l + 1];
        const float* b2 = (const float*)d_in[3 + 4 * l + 3];
        __nv_bfloat16* w1H = wH + (size_t)(2 * l) * HH * HH;
        __nv_bfloat16* w1L = wL + (size_t)(2 * l) * HH * HH;
        __nv_bfloat16* w2H = wH + (size_t)(2 * l + 1) * HH * HH;
        __nv_bfloat16* w2L = wL + (size_t)(2 * l + 1) * HH * HH;

        gather_kernel<<<gather_blocks, 256>>>(in, csrc, rowptr, deg, aH, aL);
        fused_mlp_persist<<<148, 512, FUSED_SMEM>>>(
            aH, aL, w1H, w1L, w2H, w2L, b1, b2, h, NN);
        in = h;
    }

    zero_out_kernel<<<(GG * HH + 255) / 256, 256>>>(out, cnt);
    pool_kernel<<<(NN + 127) / 128, 128>>>(h, batch, out, cnt);
    div_kernel<<<(GG * HH + 255) / 256, 256>>>(out, cnt);
}

// round 8
// speedup vs baseline: 4.5403x; 1.0030x over previous
#include <cuda_runtime.h>
#include <cuda_bf16.h>
#include <cstdint>
#include <cstddef>

#define NN 100000
#define EE 1600000
#define HH 128
#define GG 128
#define SCAN_BLK 1024
#define SCAN_NB ((NN + SCAN_BLK - 1) / SCAN_BLK)   // 98

// ---------------------------------------------------------------------------
// Scratch (__device__ globals; allocation-free rule)
// ---------------------------------------------------------------------------
__device__ float g_h[(size_t)NN * HH];              // layer output (fp32)
__device__ __nv_bfloat16 g_aH[(size_t)NN * HH];     // xagg hi split
__device__ __nv_bfloat16 g_aL[(size_t)NN * HH];     // xagg lo split
__device__ __nv_bfloat16 g_wH[6 * HH * HH];         // transposed weights hi ([n][k])
__device__ __nv_bfloat16 g_wL[6 * HH * HH];         // transposed weights lo
__device__ float g_cnt[GG];
__device__ int g_deg[NN];
__device__ int g_rowptr[NN];
__device__ int g_head[NN];
__device__ int g_csrc[EE];
__device__ int g_bsum[SCAN_NB];

// ---------------------------------------------------------------------------
// helpers
// ---------------------------------------------------------------------------
__device__ __forceinline__ uint32_t smem_u32(const void* p) {
    uint32_t a;
    asm("{ .reg .u64 t; cvta.to.shared.u64 t, %1; cvt.u32.u64 %0, t; }" : "=r"(a) : "l"(p));
    return a;
}

__device__ __forceinline__ void ldsm4(uint32_t* r, uint32_t addr) {
    asm volatile("ldmatrix.sync.aligned.m8n8.x4.shared.b16 {%0,%1,%2,%3}, [%4];"
                 : "=r"(r[0]), "=r"(r[1]), "=r"(r[2]), "=r"(r[3]) : "r"(addr));
}

__device__ __forceinline__ void mma16816(float* c, const uint32_t* a, uint32_t b0, uint32_t b1) {
    asm volatile("mma.sync.aligned.m16n8k16.row.col.f32.bf16.bf16.f32 "
                 "{%0,%1,%2,%3}, {%4,%5,%6,%7}, {%8,%9}, {%0,%1,%2,%3};"
                 : "+f"(c[0]), "+f"(c[1]), "+f"(c[2]), "+f"(c[3])
                 : "r"(a[0]), "r"(a[1]), "r"(a[2]), "r"(a[3]), "r"(b0), "r"(b1));
}

__device__ __forceinline__ uint32_t pk(__nv_bfloat16 a, __nv_bfloat16 b) {
    __nv_bfloat162 t(a, b);
    return *reinterpret_cast<uint32_t*>(&t);
}

__device__ __forceinline__ uint32_t split_hi(float v0, float v1, uint32_t& lo) {
    __nv_bfloat16 h0 = __float2bfloat16(v0), h1 = __float2bfloat16(v1);
    lo = pk(__float2bfloat16(v0 - __bfloat162float(h0)),
            __float2bfloat16(v1 - __bfloat162float(h1)));
    return pk(h0, h1);
}

__device__ __forceinline__ void cp16(uint32_t dst, const void* src, int sz) {
    asm volatile("cp.async.cg.shared.global [%0], [%1], 16, %2;"
                 :: "r"(dst), "l"(src), "r"(sz) : "memory");
}
#define CP_COMMIT() asm volatile("cp.async.commit_group;" ::: "memory")
#define CP_WAIT0()  asm volatile("cp.async.wait_group 0;" ::: "memory")

// ---------------------------------------------------------------------------
// CSR build (once per launch): edges grouped by destination
// ---------------------------------------------------------------------------
__global__ void zero_deg_kernel(int* __restrict__ deg) {
    int i = blockIdx.x * blockDim.x + threadIdx.x;
    if (i < NN) deg[i] = 0;
}

__global__ void hist_kernel(const int* __restrict__ dst, int* __restrict__ deg) {
    int i = blockIdx.x * blockDim.x + threadIdx.x;
    if (i < EE) atomicAdd(&deg[dst[i]], 1);
}

__global__ void scan1_kernel(const int* __restrict__ deg, int* __restrict__ rowptr,
                             int* __restrict__ bsum) {
    __shared__ int sh[SCAN_BLK];
    int i = blockIdx.x * SCAN_BLK + threadIdx.x;
    int v = (i < NN) ? deg[i] : 0;
    sh[threadIdx.x] = v;
    __syncthreads();
    #pragma unroll
    for (int off = 1; off < SCAN_BLK; off <<= 1) {
        int t = (threadIdx.x >= off) ? sh[threadIdx.x - off] : 0;
        __syncthreads();
        sh[threadIdx.x] += t;
        __syncthreads();
    }
    if (i < NN) rowptr[i] = sh[threadIdx.x] - v;       // exclusive
    if (threadIdx.x == SCAN_BLK - 1) bsum[blockIdx.x] = sh[SCAN_BLK - 1];
}

__global__ void scan2_kernel(int* __restrict__ bsum) {
    __shared__ int sh[128];
    int i = threadIdx.x;
    int v = (i < SCAN_NB) ? bsum[i] : 0;
    sh[i] = v;
    __syncthreads();
    #pragma unroll
    for (int off = 1; off < 128; off <<= 1) {
        int t = (i >= off) ? sh[i - off] : 0;
        __syncthreads();
        sh[i] += t;
        __syncthreads();
    }
    if (i < SCAN_NB) bsum[i] = sh[i] - v;              // exclusive
}

__global__ void scan3_kernel(int* __restrict__ rowptr, int* __restrict__ head,
                             const int* __restrict__ bsum) {
    int i = blockIdx.x * blockDim.x + threadIdx.x;
    if (i < NN) {
        int r = rowptr[i] + bsum[i >> 10];
        rowptr[i] = r;
        head[i] = r;
    }
}

__global__ void fill_kernel(const int* __restrict__ src, const int* __restrict__ dst,
                            int* __restrict__ head, int* __restrict__ csrc) {
    int i = blockIdx.x * blockDim.x + threadIdx.x;
    if (i < EE) {
        int pos = atomicAdd(&head[dst[i]], 1);
        csrc[pos] = src[i];
    }
}

// ---------------------------------------------------------------------------
// gather: warp per node. xagg[i] = in[i] + sum_{j in csr(i)} in[j]
// Output written as bf16 hi/lo split (MLP A-operand ready).
// ---------------------------------------------------------------------------
__global__ __launch_bounds__(256)
void gather_kernel(const float* __restrict__ In, const int* __restrict__ csrc,
                   const int* __restrict__ rowptr, const int* __restrict__ deg,
                   __nv_bfloat16* __restrict__ outH, __nv_bfloat16* __restrict__ outL) {
    int node = (blockIdx.x * blockDim.x + threadIdx.x) >> 5;
    int lane = threadIdx.x & 31;
    if (node >= NN) return;
    const float4* base = reinterpret_cast<const float4*>(In);

    float4 a0 = base[(size_t)node * 32 + lane];    // self term
    float4 a1 = make_float4(0.f, 0.f, 0.f, 0.f);
    float4 a2 = a1, a3 = a1;

    int st = rowptr[node];
    int dg = deg[node];
    int j = 0;
    for (; j + 4 <= dg; j += 4) {
        int s0 = __ldg(csrc + st + j);
        int s1 = __ldg(csrc + st + j + 1);
        int s2 = __ldg(csrc + st + j + 2);
        int s3 = __ldg(csrc + st + j + 3);
        float4 v0 = base[(size_t)s0 * 32 + lane];
        float4 v1 = base[(size_t)s1 * 32 + lane];
        float4 v2 = base[(size_t)s2 * 32 + lane];
        float4 v3 = base[(size_t)s3 * 32 + lane];
        a0.x += v0.x; a0.y += v0.y; a0.z += v0.z; a0.w += v0.w;
        a1.x += v1.x; a1.y += v1.y; a1.z += v1.z; a1.w += v1.w;
        a2.x += v2.x; a2.y += v2.y; a2.z += v2.z; a2.w += v2.w;
        a3.x += v3.x; a3.y += v3.y; a3.z += v3.z; a3.w += v3.w;
    }
    for (; j < dg; j++) {
        int s = __ldg(csrc + st + j);
        float4 v = base[(size_t)s * 32 + lane];
        a0.x += v.x; a0.y += v.y; a0.z += v.z; a0.w += v.w;
    }
    a0.x += a1.x + a2.x + a3.x;
    a0.y += a1.y + a2.y + a3.y;
    a0.z += a1.z + a2.z + a3.z;
    a0.w += a1.w + a2.w + a3.w;

    uint32_t lo0, lo1;
    uint32_t hi0 = split_hi(a0.x, a0.y, lo0);
    uint32_t hi1 = split_hi(a0.z, a0.w, lo1);
    *reinterpret_cast<uint2*>(outH + (size_t)node * HH + lane * 4) = make_uint2(hi0, hi1);
    *reinterpret_cast<uint2*>(outL + (size_t)node * HH + lane * 4) = make_uint2(lo0, lo1);
}

// ---------------------------------------------------------------------------
// Weights: transpose + split. out[m][n][k] = W_m[k][n]
// ---------------------------------------------------------------------------
__global__ void wconv_kernel(const float* __restrict__ W0, const float* __restrict__ W1,
                             const float* __restrict__ W2, const float* __restrict__ W3,
                             const float* __restrict__ W4, const float* __restrict__ W5,
                             __nv_bfloat16* __restrict__ wh, __nv_bfloat16* __restrict__ wl) {
    int i = blockIdx.x * blockDim.x + threadIdx.x;
    if (i >= 6 * HH * HH) return;
    int m = i / (HH * HH);
    int r = i % (HH * HH);
    int n = r / HH;
    int k = r % HH;
    const float* W = (m == 0) ? W0 : (m == 1) ? W1 : (m == 2) ? W2
                   : (m == 3) ? W3 : (m == 4) ? W4 : W5;
    float v = W[k * HH + n];
    __nv_bfloat16 h = __float2bfloat16(v);
    wh[i] = h;
    wl[i] = __float2bfloat16(v - __bfloat162float(h));
}

// ---------------------------------------------------------------------------
// Persistent fused MLP: out[M,128] = relu(A @ W1 + b1) @ W2 + b2
// A arrives pre-split. W1+W2 resident; grid-stride over 64-row M-tiles.
// Single A buffer + dedicated mid buffer (no A-overwrite hazard -> 2 syncs).
// Prefetch A(t+1) issued right after the mid barrier, hidden under GEMM2.
// Split accumulators (hi-pass vs lo-passes) for HMMA ILP.
// Smem: A 34816 + MID 34816 + W1 69632 + W2 69632 = 208896 B. 512 threads.
// ---------------------------------------------------------------------------
#define PITCH 272
#define S_A   0
#define S_MID 34816
#define S_W1H 69632
#define S_W1L 104448
#define S_W2H 139264
#define S_W2L 174080
#define FUSED_SMEM 208896
#define MTILE 64
#define NTILES ((NN + MTILE - 1) / MTILE)   // 1563

__device__ __forceinline__ void run_gemm(uint32_t aHb, uint32_t aLb,
                                         uint32_t bHb, uint32_t bLb,
                                         float (&accH)[4][4], float (&accL)[4][4]) {
    #pragma unroll
    for (int i = 0; i < 4; i++)
        #pragma unroll
        for (int j = 0; j < 4; j++) { accH[i][j] = 0.f; accL[i][j] = 0.f; }
    #pragma unroll
    for (int ks = 0; ks < 8; ks++) {
        uint32_t aH[4], aL[4];
        ldsm4(aH, aHb + ks * 32);
        ldsm4(aL, aLb + ks * 32);
        #pragma unroll
        for (int np = 0; np < 2; np++) {
            uint32_t bh[4], bl[4];
            ldsm4(bh, bHb + np * (16 * PITCH) + ks * 32);
            ldsm4(bl, bLb + np * (16 * PITCH) + ks * 32);
            // hi-pass -> accH (1 dep), correction passes -> accL (2 deps)
            mma16816(accH[2 * np],     aH, bh[0], bh[2]);
            mma16816(accL[2 * np],     aL, bh[0], bh[2]);
            mma16816(accL[2 * np],     aH, bl[0], bl[2]);
            mma16816(accH[2 * np + 1], aH, bh[1], bh[3]);
            mma16816(accL[2 * np + 1], aL, bh[1], bh[3]);
            mma16816(accL[2 * np + 1], aH, bl[1], bl[3]);
        }
    }
}

__device__ __forceinline__ void prefetch_A(uint32_t sb, int tile,
                                           const __nv_bfloat16* __restrict__ AH,
                                           const __nv_bfloat16* __restrict__ AL,
                                           int M, int tid) {
    #pragma unroll
    for (int it = 0; it < 2; it++) {
        int idx = it * 512 + tid;       // 0..1023
        int row = idx >> 4, c = idx & 15;
        int gm = tile * MTILE + row;
        int ok = (gm < M) ? 16 : 0;
        int gs = min(gm, M - 1);
        uint32_t d = sb + S_A + row * PITCH + c * 16;
        cp16(d,         AH + (size_t)gs * HH + c * 8, ok);
        cp16(d + 17408, AL + (size_t)gs * HH + c * 8, ok);
    }
}

__global__ __launch_bounds__(512, 1)
void fused_mlp_persist(const __nv_bfloat16* __restrict__ AH,
                       const __nv_bfloat16* __restrict__ AL,
                       const __nv_bfloat16* __restrict__ W1h, const __nv_bfloat16* __restrict__ W1l,
                       const __nv_bfloat16* __restrict__ W2h, const __nv_bfloat16* __restrict__ W2l,
                       const float* __restrict__ bias1, const float* __restrict__ bias2,
                       float* __restrict__ Out, int M) {
    extern __shared__ __align__(16) char smem[];
    const uint32_t sb = smem_u32(smem);
    const int tid = threadIdx.x;
    const int wid = tid >> 5, lane = tid & 31;

    // ---- stage all weights once ----
    #pragma unroll
    for (int it = 0; it < 4; it++) {
        int idx = it * 512 + tid;       // 0..2047
        int row = idx >> 4, c = idx & 15;
        size_t go = (size_t)row * HH + c * 8;
        *reinterpret_cast<uint4*>(smem + S_W1H + row * PITCH + c * 16) =
            *reinterpret_cast<const uint4*>(W1h + go);
        *reinterpret_cast<uint4*>(smem + S_W1L + row * PITCH + c * 16) =
            *reinterpret_cast<const uint4*>(W1l + go);
        *reinterpret_cast<uint4*>(smem + S_W2H + row * PITCH + c * 16) =
            *reinterpret_cast<const uint4*>(W2h + go);
        *reinterpret_cast<uint4*>(smem + S_W2L + row * PITCH + c * 16) =
            *reinterpret_cast<const uint4*>(W2l + go);
    }

    int t = blockIdx.x;
    if (t < NTILES) prefetch_A(sb, t, AH, AL, M, tid);
    CP_COMMIT();

    const int wr = wid >> 2;            // 0..3 (16 rows each)
    const int wc = wid & 3;             // 0..3 (32 cols each)
    const int arow = lane & 15;
    const int akc  = (lane & 16) >> 1;  // 0 or 8
    const int quad = lane >> 2;
    const int qc   = (lane & 3) * 2;

    const uint32_t aHb = sb + S_A   + (wr * 16 + arow) * PITCH + akc * 2;
    const uint32_t aLb = aHb + 17408;
    const uint32_t mHb = sb + S_MID + (wr * 16 + arow) * PITCH + akc * 2;
    const uint32_t mLb = mHb + 17408;
    const uint32_t w1Hb = sb + S_W1H + (wc * 32 + arow) * PITCH + akc * 2;
    const uint32_t w1Lb = sb + S_W1L + (wc * 32 + arow) * PITCH + akc * 2;
    const uint32_t w2Hb = sb + S_W2H + (wc * 32 + arow) * PITCH + akc * 2;
    const uint32_t w2Lb = sb + S_W2L + (wc * 32 + arow) * PITCH + akc * 2;

    while (t < NTILES) {
        int tn = t + gridDim.x;
        CP_WAIT0();
        __syncthreads();                                  // B1: A(t) ready

        float accH[4][4], accL[4][4];

        // ---- GEMM1: A x W1 ----
        run_gemm(aHb, aLb, w1Hb, w1Lb, accH, accL);

        // ---- epilogue 1: relu(acc+b1) -> hi/lo -> MID buffer ----
        {
            const int lr0 = wr * 16 + quad;
            #pragma unroll
            for (int np = 0; np < 2; np++) {
                #pragma unroll
                for (int s = 0; s < 2; s++) {
                    int nt = 2 * np + s;
                    int col = wc * 32 + np * 16 + s * 8 + qc;
                    float b0 = __ldg(bias1 + col), b1v = __ldg(bias1 + col + 1);
                    float v00 = fmaxf(accH[nt][0] + accL[nt][0] + b0, 0.f);
                    float v01 = fmaxf(accH[nt][1] + accL[nt][1] + b1v, 0.f);
                    float v10 = fmaxf(accH[nt][2] + accL[nt][2] + b0, 0.f);
                    float v11 = fmaxf(accH[nt][3] + accL[nt][3] + b1v, 0.f);
                    uint32_t lo0, lo1;
                    uint32_t hi0 = split_hi(v00, v01, lo0);
                    uint32_t hi1 = split_hi(v10, v11, lo1);
                    char* mb = smem + S_MID;
                    *reinterpret_cast<uint32_t*>(mb + lr0 * PITCH + col * 2) = hi0;
                    *reinterpret_cast<uint32_t*>(mb + 17408 + lr0 * PITCH + col * 2) = lo0;
                    *reinterpret_cast<uint32_t*>(mb + (lr0 + 8) * PITCH + col * 2) = hi1;
                    *reinterpret_cast<uint32_t*>(mb + 17408 + (lr0 + 8) * PITCH + col * 2) = lo1;
                }
            }
        }
        __syncthreads();                                  // B2: mid visible, A reads done

        // prefetch next tile's A (hidden under GEMM2 + epilogue 2)
        if (tn < NTILES) prefetch_A(sb, tn, AH, AL, M, tid);
        CP_COMMIT();

        // ---- GEMM2: mid x W2 ----
        run_gemm(mHb, mLb, w2Hb, w2Lb, accH, accL);

        // ---- epilogue 2: + b2 -> fp32 gmem ----
        {
            const int r0 = t * MTILE + wr * 16 + quad;
            const int r1 = r0 + 8;
            #pragma unroll
            for (int np = 0; np < 2; np++) {
                #pragma unroll
                for (int s = 0; s < 2; s++) {
                    int nt = 2 * np + s;
                    int col = wc * 32 + np * 16 + s * 8 + qc;
                    float b0 = __ldg(bias2 + col), b1v = __ldg(bias2 + col + 1);
                    if (r0 < M)
                        *reinterpret_cast<float2*>(Out + (size_t)r0 * HH + col) =
                            make_float2(accH[nt][0] + accL[nt][0] + b0,
                                        accH[nt][1] + accL[nt][1] + b1v);
                    if (r1 < M)
                        *reinterpret_cast<float2*>(Out + (size_t)r1 * HH + col) =
                            make_float2(accH[nt][2] + accL[nt][2] + b0,
                                        accH[nt][3] + accL[nt][3] + b1v);
                }
            }
        }
        t = tn;
    }
}

// ---------------------------------------------------------------------------
// Pooling (batch sorted)
// ---------------------------------------------------------------------------
__global__ void pool_kernel(const float* __restrict__ h, const int* __restrict__ batch,
                            float* __restrict__ out, float* __restrict__ cnt) {
    __shared__ int sbv[128];
    const int b0 = blockIdx.x * 128;
    const int c = threadIdx.x;
    const int nrows = min(128, NN - b0);
    if (c < nrows) sbv[c] = batch[b0 + c];
    __syncthreads();

    int cur = sbv[0];
    float acc = 0.f, cn = 0.f;
    for (int i = 0; i < nrows; i++) {
        int g = sbv[i];
        if (g != cur) {
            atomicAdd(&out[cur * 128 + c], acc);
            if (c == 0) atomicAdd(&cnt[cur], cn);
            acc = 0.f; cn = 0.f; cur = g;
        }
        acc += h[(size_t)(b0 + i) * 128 + c];
        cn += 1.f;
    }
    atomicAdd(&out[cur * 128 + c], acc);
    if (c == 0) atomicAdd(&cnt[cur], cn);
}

__global__ void zero_out_kernel(float* __restrict__ out, float* __restrict__ cnt) {
    int i = blockIdx.x * blockDim.x + threadIdx.x;
    if (i < GG * HH) out[i] = 0.f;
    if (i < GG) cnt[i] = 0.f;
}

__global__ void div_kernel(float* __restrict__ out, const float* __restrict__ cnt) {
    int i = blockIdx.x * blockDim.x + threadIdx.x;
    if (i < GG * HH) out[i] /= fmaxf(cnt[i >> 7], 1.f);
}

// ---------------------------------------------------------------------------
// Launch
// ---------------------------------------------------------------------------
extern "C" void kernel_launch(void* const* d_in, const int* in_sizes, int n_in,
                              void* d_out, int out_size) {
    (void)in_sizes; (void)n_in; (void)out_size;

    const float* x          = (const float*)d_in[0];
    const int*   edge_index = (const int*)d_in[1];
    const int*   batch      = (const int*)d_in[2];
    const int*   e_src = edge_index;
    const int*   e_dst = edge_index + EE;
    float* out = (float*)d_out;

    void *ph, *paH, *paL, *pwH, *pwL, *pcnt, *pdeg, *prp, *phd, *pcs, *pbs;
    cudaGetSymbolAddress(&ph,  g_h);
    cudaGetSymbolAddress(&paH, g_aH);
    cudaGetSymbolAddress(&paL, g_aL);
    cudaGetSymbolAddress(&pwH, g_wH);
    cudaGetSymbolAddress(&pwL, g_wL);
    cudaGetSymbolAddress(&pcnt, g_cnt);
    cudaGetSymbolAddress(&pdeg, g_deg);
    cudaGetSymbolAddress(&prp,  g_rowptr);
    cudaGetSymbolAddress(&phd,  g_head);
    cudaGetSymbolAddress(&pcs,  g_csrc);
    cudaGetSymbolAddress(&pbs,  g_bsum);
    float* h  = (float*)ph;
    __nv_bfloat16* aH = (__nv_bfloat16*)paH;
    __nv_bfloat16* aL = (__nv_bfloat16*)paL;
    __nv_bfloat16* wH = (__nv_bfloat16*)pwH;
    __nv_bfloat16* wL = (__nv_bfloat16*)pwL;
    float* cnt = (float*)pcnt;
    int* deg    = (int*)pdeg;
    int* rowptr = (int*)prp;
    int* head   = (int*)phd;
    int* csrc   = (int*)pcs;
    int* bsum   = (int*)pbs;

    cudaFuncSetAttribute(fused_mlp_persist,
                         cudaFuncAttributeMaxDynamicSharedMemorySize, FUSED_SMEM);

    const int nn_blocks     = (NN + 255) / 256;
    const int ee_blocks     = (EE + 255) / 256;
    const int gather_blocks = (NN * 32 + 255) / 256;  // warp per node
    const int wconv_blocks  = (6 * HH * HH + 255) / 256;

    // ---- CSR build (once) ----
    zero_deg_kernel<<<nn_blocks, 256>>>(deg);
    hist_kernel<<<ee_blocks, 256>>>(e_dst, deg);
    scan1_kernel<<<SCAN_NB, SCAN_BLK>>>(deg, rowptr, bsum);
    scan2_kernel<<<1, 128>>>(bsum);
    scan3_kernel<<<nn_blocks, 256>>>(rowptr, head, bsum);
    fill_kernel<<<ee_blocks, 256>>>(e_src, e_dst, head, csrc);

    wconv_kernel<<<wconv_blocks, 256>>>((const float*)d_in[3], (const float*)d_in[5],
                                        (const float*)d_in[7], (const float*)d_in[9],
                                        (const float*)d_in[11], (const float*)d_in[13],
                                        wH, wL);

    const float* in = x;
    for (int l = 0; l < 3; l++) {
        const float* b1 = (const float*)d_in[3 + 4 * l + 1];
        const float* b2 = (const float*)d_in[3 + 4 * l + 3];
        __nv_bfloat16* w1H = wH + (size_t)(2 * l) * HH * HH;
        __nv_bfloat16* w1L = wL + (size_t)(2 * l) * HH * HH;
        __nv_bfloat16* w2H = wH + (size_t)(2 * l + 1) * HH * HH;
        __nv_bfloat16* w2L = wL + (size_t)(2 * l + 1) * HH * HH;

        gather_kernel<<<gather_blocks, 256>>>(in, csrc, rowptr, deg, aH, aL);
        fused_mlp_persist<<<148, 512, FUSED_SMEM>>>(
            aH, aL, w1H, w1L, w2H, w2L, b1, b2, h, NN);
        in = h;
    }

    zero_out_kernel<<<(GG * HH + 255) / 256, 256>>>(out, cnt);
    pool_kernel<<<(NN + 127) / 128, 128>>>(h, batch, out, cnt);
    div_kernel<<<(GG * HH + 255) / 256, 256>>>(out, cnt);
}